// round 4
// baseline (speedup 1.0000x reference)
#include <cuda_runtime.h>
#include <cstdint>

#define NN 50000
#define EE 800000

// ---------------- scratch (static device globals; no allocs) ----------------
__device__ float g_m1[NN * 128];
__device__ float g_qp1[NN * 256];   // [node][0:128]=q1, [128:256]=p1
__device__ float g_m2[NN * 128];
__device__ float g_qp2[NN * 128];   // [node][0:64]=q2, [64:128]=p2
__device__ float g_wqp1[128 * 256];
__device__ float g_bqp1[256];
__device__ float g_wqp2[128 * 128];
__device__ float g_bqp2[128];
__device__ int   g_rowptr[NN + 1];
__device__ int   g_cursor[NN];
__device__ int   g_esrc[EE];

__device__ __forceinline__ float gelu_f(float x) {
    return 0.5f * x * (1.0f + erff(x * 0.70710678118654752440f));
}

// ---------------- packed f32x2 helpers ----------------
__device__ __forceinline__ void ffma2(unsigned long long& d, unsigned long long a, unsigned long long b) {
    asm("fma.rn.f32x2 %0, %1, %2, %0;" : "+l"(d) : "l"(a), "l"(b));
}
__device__ __forceinline__ unsigned long long pack2(float x, float y) {
    unsigned long long r;
    asm("mov.b64 %0, {%1,%2};" : "=l"(r) : "f"(x), "f"(y));
    return r;
}
__device__ __forceinline__ float2 unpack2(unsigned long long v) {
    float2 r;
    asm("mov.b64 {%0,%1}, %2;" : "=f"(r.x), "=f"(r.y) : "l"(v));
    return r;
}

// ---------------- CSR build ----------------
__global__ void zero_k() {
    int i = blockIdx.x * blockDim.x + threadIdx.x;
    if (i < NN) g_cursor[i] = 0;
}
__global__ void hist_k(const int* __restrict__ dst) {
    int e = blockIdx.x * blockDim.x + threadIdx.x;
    if (e < EE) atomicAdd(&g_cursor[dst[e]], 1);
}
__global__ __launch_bounds__(1024) void scan_k() {
    __shared__ int warpsum[32];
    __shared__ int s_carry;
    __shared__ int s_tot;
    int tid = threadIdx.x, lane = tid & 31, wid = tid >> 5;
    if (tid == 0) s_carry = 0;
    __syncthreads();
    for (int base = 0; base < NN; base += 8192) {
        int idx0 = base + tid * 8;
        int v[8]; int tot = 0;
#pragma unroll
        for (int j = 0; j < 8; j++) {
            int id = idx0 + j;
            v[j] = (id < NN) ? g_cursor[id] : 0;
            tot += v[j];
        }
        int incl = tot;
#pragma unroll
        for (int off = 1; off < 32; off <<= 1) {
            int t = __shfl_up_sync(0xffffffffu, incl, off);
            if (lane >= off) incl += t;
        }
        if (lane == 31) warpsum[wid] = incl;
        __syncthreads();
        if (wid == 0) {
            int w = warpsum[lane];
            int wi = w;
#pragma unroll
            for (int off = 1; off < 32; off <<= 1) {
                int t = __shfl_up_sync(0xffffffffu, wi, off);
                if (lane >= off) wi += t;
            }
            warpsum[lane] = wi - w;
            if (lane == 31) s_tot = wi;
        }
        __syncthreads();
        int run = s_carry + warpsum[wid] + (incl - tot);
#pragma unroll
        for (int j = 0; j < 8; j++) {
            int id = idx0 + j;
            if (id < NN) { g_rowptr[id] = run; g_cursor[id] = 0; }
            run += v[j];
        }
        __syncthreads();
        if (tid == 0) s_carry += s_tot;
        __syncthreads();
    }
    if (threadIdx.x == 0) g_rowptr[NN] = s_carry;
}
__global__ void scatter_k(const int* __restrict__ src, const int* __restrict__ dst) {
    int e = blockIdx.x * blockDim.x + threadIdx.x;
    if (e < EE) {
        int d = dst[e];
        int pos = g_rowptr[d] + atomicAdd(&g_cursor[d], 1);
        g_esrc[pos] = src[e];
    }
}

// ---------------- weight/bias concat: Wc[k][0:na]=Wa, [na:na+nb]=Wb ----------
__global__ void concat_k(const float* __restrict__ Wa, const float* __restrict__ Wb,
                         const float* __restrict__ ba, const float* __restrict__ bb,
                         float* __restrict__ Wc, float* __restrict__ bc, int na, int nb) {
    int nc = na + nb;
    int i = blockIdx.x * blockDim.x + threadIdx.x;
    if (i < 128 * nc) {
        int k = i / nc, c = i % nc;
        Wc[i] = (c < na) ? Wa[k * na + c] : Wb[k * nb + (c - na)];
    }
    if (i < nc) bc[i] = (i < na) ? ba[i] : bb[i - na];
}

// ---------------- fp32 GEMM on FFMA2: C = act(A[M,128] @ W[128,ncols] + bias) --
// BM=128, BN=128, BK=16; 256 threads; 8x8 per-thread tile as f32x2 pairs over M.
__global__ __launch_bounds__(256) void gemmf2_k(
    const float* __restrict__ A, const float* __restrict__ W,
    const float* __restrict__ bias, float* __restrict__ C,
    int M, int ncols, int act)
{
    __shared__ float  As[16][128];       // [k][row]
    __shared__ float2 Bs[16][128];       // [k][col] duplicated {b,b}

    const int tid = threadIdx.x;
    const int tx = tid & 15, ty = tid >> 4;
    const int rowBase = blockIdx.x * 128;
    const int colBase = blockIdx.y * 128;

    unsigned long long acc[4][8];
#pragma unroll
    for (int i = 0; i < 4; i++)
#pragma unroll
        for (int j = 0; j < 8; j++) acc[i][j] = pack2(0.f, 0.f);

    const int lr = tid >> 1;             // A: row 0..127
    const int lk = (tid & 1) * 8;        // A: k offset 0/8
    const int bk = tid >> 4;             // B: k row 0..15
    const int bn = (tid & 15) * 8;       // B: col offset

    int gr = rowBase + lr; if (gr >= M) gr = M - 1;   // clamp; stores guarded
    const float* aptr = A + (size_t)gr * 128 + lk;
    const float* wptr = W + (size_t)bk * ncols + colBase + bn;

    float4 a0 = *(const float4*)(aptr);
    float4 a1 = *(const float4*)(aptr + 4);
    float4 b0 = *(const float4*)(wptr);
    float4 b1 = *(const float4*)(wptr + 4);

    for (int kt = 0; kt < 8; kt++) {
        As[lk + 0][lr] = a0.x; As[lk + 1][lr] = a0.y;
        As[lk + 2][lr] = a0.z; As[lk + 3][lr] = a0.w;
        As[lk + 4][lr] = a1.x; As[lk + 5][lr] = a1.y;
        As[lk + 6][lr] = a1.z; As[lk + 7][lr] = a1.w;
        Bs[bk][bn + 0] = make_float2(b0.x, b0.x);
        Bs[bk][bn + 1] = make_float2(b0.y, b0.y);
        Bs[bk][bn + 2] = make_float2(b0.z, b0.z);
        Bs[bk][bn + 3] = make_float2(b0.w, b0.w);
        Bs[bk][bn + 4] = make_float2(b1.x, b1.x);
        Bs[bk][bn + 5] = make_float2(b1.y, b1.y);
        Bs[bk][bn + 6] = make_float2(b1.z, b1.z);
        Bs[bk][bn + 7] = make_float2(b1.w, b1.w);
        __syncthreads();
        if (kt < 7) {   // prefetch next k-tile into registers
            a0 = *(const float4*)(aptr + (kt + 1) * 16);
            a1 = *(const float4*)(aptr + (kt + 1) * 16 + 4);
            b0 = *(const float4*)(wptr + (size_t)(kt + 1) * 16 * ncols);
            b1 = *(const float4*)(wptr + (size_t)(kt + 1) * 16 * ncols + 4);
        }
#pragma unroll
        for (int k = 0; k < 16; k++) {
            unsigned long long ap[4], bp[8];
#pragma unroll
            for (int i = 0; i < 4; i++)
                ap[i] = *(const unsigned long long*)&As[k][ty * 8 + 2 * i];   // {row, row+1}
#pragma unroll
            for (int j = 0; j < 8; j++)
                bp[j] = *(const unsigned long long*)&Bs[k][tx + 16 * j];      // {b, b}
#pragma unroll
            for (int i = 0; i < 4; i++)
#pragma unroll
                for (int j = 0; j < 8; j++)
                    ffma2(acc[i][j], ap[i], bp[j]);
        }
        __syncthreads();
    }

    // epilogue: acc[i][j] holds rows (ty*8+2i, ty*8+2i+1), col colBase+tx+16j
#pragma unroll
    for (int j = 0; j < 8; j++) {
        int c = colBase + tx + 16 * j;
        float bb = bias[c];
#pragma unroll
        for (int i = 0; i < 4; i++) {
            int r = rowBase + ty * 8 + 2 * i;
            float2 v = unpack2(acc[i][j]);
            v.x += bb; v.y += bb;
            if (act) { v.x = gelu_f(v.x); v.y = gelu_f(v.y); }
            if (r < M)     C[(size_t)r * ncols + c] = v.x;
            if (r + 1 < M) C[(size_t)(r + 1) * ncols + c] = v.y;
        }
    }
}

// ---------------- edge kernels: one warp per dst node, fused softmax-agg ----
// layer1: qp stride 256, q at +0, p at +128; out = gelu(h1+bg) -> m2
__global__ __launch_bounds__(256) void edge128_k(
    const float* __restrict__ qp, const float* __restrict__ a,
    const float* __restrict__ bg, float* __restrict__ out)
{
    int gw = (blockIdx.x * 256 + threadIdx.x) >> 5;
    if (gw >= NN) return;
    int lane = threadIdx.x & 31;
    int c = lane * 4;
    float4 qv = *(const float4*)(qp + (size_t)gw * 256 + c);
    float4 av = *(const float4*)(a + c);
    float ax = 0.f, ay = 0.f, az = 0.f, aw = 0.f;
    float denom = 0.f;
    int i = g_rowptr[gw];
    int end = g_rowptr[gw + 1];
    if (i < end) {
        int s = g_esrc[i];
        float4 pv = *(const float4*)(qp + (size_t)s * 256 + 128 + c);
        while (1) {
            float4 pvn;
            if (i + 1 < end) {
                int sn = g_esrc[i + 1];
                pvn = *(const float4*)(qp + (size_t)sn * 256 + 128 + c);
            }
            float tx = qv.x + pv.x; tx = tx > 0.f ? tx : 0.2f * tx;
            float ty = qv.y + pv.y; ty = ty > 0.f ? ty : 0.2f * ty;
            float tz = qv.z + pv.z; tz = tz > 0.f ? tz : 0.2f * tz;
            float tw = qv.w + pv.w; tw = tw > 0.f ? tw : 0.2f * tw;
            float part = fmaf(tx, av.x, fmaf(ty, av.y, fmaf(tz, av.z, tw * av.w)));
#pragma unroll
            for (int off = 16; off > 0; off >>= 1)
                part += __shfl_xor_sync(0xffffffffu, part, off);
            float es = __expf(part);
            denom += es;
            ax = fmaf(es, pv.x, ax);
            ay = fmaf(es, pv.y, ay);
            az = fmaf(es, pv.z, az);
            aw = fmaf(es, pv.w, aw);
            i++;
            if (i >= end) break;
            pv = pvn;
        }
    }
    float inv = denom > 0.f ? 1.0f / denom : 0.f;
    float4 bv = *(const float4*)(bg + c);
    float4 o;
    o.x = gelu_f(fmaf(ax, inv, bv.x));
    o.y = gelu_f(fmaf(ay, inv, bv.y));
    o.z = gelu_f(fmaf(az, inv, bv.z));
    o.w = gelu_f(fmaf(aw, inv, bv.w));
    *(float4*)(out + (size_t)gw * 128 + c) = o;
}

// layer2: qp stride 128, q at +0, p at +64; out = h2 + b_out
__global__ __launch_bounds__(256) void edge64_k(
    const float* __restrict__ qp, const float* __restrict__ a,
    const float* __restrict__ bo, float* __restrict__ out)
{
    int gw = (blockIdx.x * 256 + threadIdx.x) >> 5;
    if (gw >= NN) return;
    int lane = threadIdx.x & 31;
    int c = lane * 2;
    float2 qv = *(const float2*)(qp + (size_t)gw * 128 + c);
    float2 av = *(const float2*)(a + c);
    float ax = 0.f, ay = 0.f;
    float denom = 0.f;
    int i = g_rowptr[gw];
    int end = g_rowptr[gw + 1];
    if (i < end) {
        int s = g_esrc[i];
        float2 pv = *(const float2*)(qp + (size_t)s * 128 + 64 + c);
        while (1) {
            float2 pvn;
            if (i + 1 < end) {
                int sn = g_esrc[i + 1];
                pvn = *(const float2*)(qp + (size_t)sn * 128 + 64 + c);
            }
            float tx = qv.x + pv.x; tx = tx > 0.f ? tx : 0.2f * tx;
            float ty = qv.y + pv.y; ty = ty > 0.f ? ty : 0.2f * ty;
            float part = fmaf(tx, av.x, ty * av.y);
#pragma unroll
            for (int off = 16; off > 0; off >>= 1)
                part += __shfl_xor_sync(0xffffffffu, part, off);
            float es = __expf(part);
            denom += es;
            ax = fmaf(es, pv.x, ax);
            ay = fmaf(es, pv.y, ay);
            i++;
            if (i >= end) break;
            pv = pvn;
        }
    }
    float inv = denom > 0.f ? 1.0f / denom : 0.f;
    float2 bv = *(const float2*)(bo + c);
    float2 o;
    o.x = fmaf(ax, inv, bv.x);
    o.y = fmaf(ay, inv, bv.y);
    *(float2*)(out + (size_t)gw * 64 + c) = o;
}

// ---------------- launch ----------------
extern "C" void kernel_launch(void* const* d_in, const int* in_sizes, int n_in,
                              void* d_out, int out_size)
{
    const float* x    = (const float*)d_in[0];
    const float* W0   = (const float*)d_in[1];
    const float* b0   = (const float*)d_in[2];
    const float* Wq1  = (const float*)d_in[3];
    const float* bq1  = (const float*)d_in[4];
    const float* Wp1  = (const float*)d_in[5];
    const float* bp1  = (const float*)d_in[6];
    const float* a1   = (const float*)d_in[7];
    const float* bg2  = (const float*)d_in[8];
    const float* Wq2  = (const float*)d_in[9];
    const float* bq2  = (const float*)d_in[10];
    const float* Wp2  = (const float*)d_in[11];
    const float* bp2  = (const float*)d_in[12];
    const float* a2   = (const float*)d_in[13];
    const float* bout = (const float*)d_in[14];
    const int*   src  = (const int*)d_in[15];
    const int*   dst  = (const int*)d_in[16];
    float* out = (float*)d_out;

    float *m1, *qp1, *m2, *qp2, *wqp1, *bqp1, *wqp2, *bqp2;
    cudaGetSymbolAddress((void**)&m1,  g_m1);
    cudaGetSymbolAddress((void**)&qp1, g_qp1);
    cudaGetSymbolAddress((void**)&m2,  g_m2);
    cudaGetSymbolAddress((void**)&qp2, g_qp2);
    cudaGetSymbolAddress((void**)&wqp1, g_wqp1);
    cudaGetSymbolAddress((void**)&bqp1, g_bqp1);
    cudaGetSymbolAddress((void**)&wqp2, g_wqp2);
    cudaGetSymbolAddress((void**)&bqp2, g_bqp2);

    // CSR build
    zero_k<<<(NN + 255) / 256, 256>>>();
    hist_k<<<(EE + 255) / 256, 256>>>(dst);
    scan_k<<<1, 1024>>>();
    scatter_k<<<(EE + 255) / 256, 256>>>(src, dst);

    // fuse q|p weights per layer
    concat_k<<<(128 * 256 + 255) / 256, 256>>>(Wq1, Wp1, bq1, bp1, wqp1, bqp1, 128, 128);
    concat_k<<<(128 * 128 + 255) / 256, 256>>>(Wq2, Wp2, bq2, bp2, wqp2, bqp2, 64, 64);

    const int MB = (NN + 127) / 128;

    // layer 1
    gemmf2_k<<<dim3(MB, 1), 256>>>(x,  W0,   b0,   m1,  NN, 128, 1);  // m1 = gelu(x@W0+b0)
    gemmf2_k<<<dim3(MB, 2), 256>>>(m1, wqp1, bqp1, qp1, NN, 256, 0);  // q1|p1
    edge128_k<<<(NN * 32 + 255) / 256, 256>>>(qp1, a1, bg2, m2);      // m2 = gelu(h1+bg2)

    // layer 2
    gemmf2_k<<<dim3(MB, 1), 256>>>(m2, wqp2, bqp2, qp2, NN, 128, 0);  // q2|p2
    edge64_k<<<(NN * 32 + 255) / 256, 256>>>(qp2, a2, bout, out);     // out = h2 + b_out
}

// round 5
// speedup vs baseline: 2.0669x; 2.0669x over previous
#include <cuda_runtime.h>
#include <cuda_bf16.h>
#include <cstdint>

#define NN 50000
#define EE 800000

// ---------------- scratch (static device globals; no allocs) ----------------
__device__ __nv_bfloat16 g_xhi[NN * 128],  g_xlo[NN * 128];
__device__ __nv_bfloat16 g_m1hi[NN * 128], g_m1lo[NN * 128];
__device__ __nv_bfloat16 g_m2hi[NN * 128], g_m2lo[NN * 128];
__device__ float g_qp1[NN * 256];   // [node][0:128]=q1, [128:256]=p1
__device__ float g_qp2[NN * 128];   // [node][0:64]=q2, [64:128]=p2
// transposed weights: Wt[n][k] = W[k][n], hi/lo bf16
__device__ __nv_bfloat16 g_w0t_hi[128 * 128],  g_w0t_lo[128 * 128];
__device__ __nv_bfloat16 g_wqp1t_hi[256 * 128], g_wqp1t_lo[256 * 128];
__device__ __nv_bfloat16 g_wqp2t_hi[128 * 128], g_wqp2t_lo[128 * 128];
__device__ float g_bqp1[256];
__device__ float g_bqp2[128];
__device__ int   g_rowptr[NN + 1];
__device__ int   g_cursor[NN];
__device__ int   g_esrc[EE];

__device__ __forceinline__ float gelu_f(float x) {
    return 0.5f * x * (1.0f + erff(x * 0.70710678118654752440f));
}
__device__ __forceinline__ void split_bf16(float v, __nv_bfloat16& hi, __nv_bfloat16& lo) {
    hi = __float2bfloat16_rn(v);
    lo = __float2bfloat16_rn(v - __bfloat162float(hi));
}
__device__ __forceinline__ uint32_t smem_u32(const void* p) {
    uint32_t a;
    asm("{ .reg .u64 t; cvta.to.shared.u64 t, %1; cvt.u32.u64 %0, t; }" : "=r"(a) : "l"(p));
    return a;
}
__device__ __forceinline__ void ldsm4(uint32_t& r0, uint32_t& r1, uint32_t& r2, uint32_t& r3, uint32_t addr) {
    asm volatile("ldmatrix.sync.aligned.m8n8.x4.shared.b16 {%0,%1,%2,%3}, [%4];"
                 : "=r"(r0), "=r"(r1), "=r"(r2), "=r"(r3) : "r"(addr));
}
__device__ __forceinline__ void mma_bf16(float* c, const uint32_t* a, const uint32_t* b) {
    asm volatile(
        "mma.sync.aligned.m16n8k16.row.col.f32.bf16.bf16.f32 "
        "{%0,%1,%2,%3}, {%4,%5,%6,%7}, {%8,%9}, {%0,%1,%2,%3};"
        : "+f"(c[0]), "+f"(c[1]), "+f"(c[2]), "+f"(c[3])
        : "r"(a[0]), "r"(a[1]), "r"(a[2]), "r"(a[3]), "r"(b[0]), "r"(b[1]));
}

// ---------------- CSR build ----------------
__global__ void zero_k() {
    int i = blockIdx.x * blockDim.x + threadIdx.x;
    if (i < NN) g_cursor[i] = 0;
}
__global__ void hist_k(const int* __restrict__ dst) {
    int e = blockIdx.x * blockDim.x + threadIdx.x;
    if (e < EE) atomicAdd(&g_cursor[dst[e]], 1);
}
__global__ __launch_bounds__(1024) void scan_k() {
    __shared__ int warpsum[32];
    __shared__ int s_carry;
    __shared__ int s_tot;
    int tid = threadIdx.x, lane = tid & 31, wid = tid >> 5;
    if (tid == 0) s_carry = 0;
    __syncthreads();
    for (int base = 0; base < NN; base += 8192) {
        int idx0 = base + tid * 8;
        int v[8]; int tot = 0;
#pragma unroll
        for (int j = 0; j < 8; j++) {
            int id = idx0 + j;
            v[j] = (id < NN) ? g_cursor[id] : 0;
            tot += v[j];
        }
        int incl = tot;
#pragma unroll
        for (int off = 1; off < 32; off <<= 1) {
            int t = __shfl_up_sync(0xffffffffu, incl, off);
            if (lane >= off) incl += t;
        }
        if (lane == 31) warpsum[wid] = incl;
        __syncthreads();
        if (wid == 0) {
            int w = warpsum[lane];
            int wi = w;
#pragma unroll
            for (int off = 1; off < 32; off <<= 1) {
                int t = __shfl_up_sync(0xffffffffu, wi, off);
                if (lane >= off) wi += t;
            }
            warpsum[lane] = wi - w;
            if (lane == 31) s_tot = wi;
        }
        __syncthreads();
        int run = s_carry + warpsum[wid] + (incl - tot);
#pragma unroll
        for (int j = 0; j < 8; j++) {
            int id = idx0 + j;
            if (id < NN) { g_rowptr[id] = run; g_cursor[id] = 0; }
            run += v[j];
        }
        __syncthreads();
        if (tid == 0) s_carry += s_tot;
        __syncthreads();
    }
    if (threadIdx.x == 0) g_rowptr[NN] = s_carry;
}
__global__ void scatter_k(const int* __restrict__ src, const int* __restrict__ dst) {
    int e = blockIdx.x * blockDim.x + threadIdx.x;
    if (e < EE) {
        int d = dst[e];
        int pos = g_rowptr[d] + atomicAdd(&g_cursor[d], 1);
        g_esrc[pos] = src[e];
    }
}

// ---------------- conversions ----------------
__global__ void convx_k(const float* __restrict__ x) {
    int i = blockIdx.x * blockDim.x + threadIdx.x;
    if (i < NN * 128) {
        __nv_bfloat16 h, l;
        split_bf16(x[i], h, l);
        g_xhi[i] = h; g_xlo[i] = l;
    }
}
// Wt[n][k] = (n<na ? Wa[k][n] : Wb[k][n-na]); also concat biases
__global__ void convw_k(const float* __restrict__ Wa, const float* __restrict__ Wb,
                        const float* __restrict__ ba, const float* __restrict__ bb,
                        __nv_bfloat16* __restrict__ hi, __nv_bfloat16* __restrict__ lo,
                        float* __restrict__ bc, int na, int nb) {
    int nc = na + nb;
    int i = blockIdx.x * blockDim.x + threadIdx.x;
    if (i < nc * 128) {
        int n = i >> 7, k = i & 127;
        float v = (n < na) ? Wa[(size_t)k * na + n] : Wb[(size_t)k * nb + (n - na)];
        __nv_bfloat16 h, l;
        split_bf16(v, h, l);
        hi[i] = h; lo[i] = l;
    }
    if (bc && i < nc) bc[i] = (i < na) ? ba[i] : bb[i - na];
}

// ---------------- bf16x3 mma.sync GEMM ----------------
// C[M, ncols] = act(A[M,128] @ Wt^T + bias). BM=128, BN=128, full K=128 staged.
// 256 threads = 8 warps (wm 0..3, wn 0..1), warp tile 32x64.
// smem row stride 136 halves -> ldmatrix conflict-free.
#define ASTRIDE 136
#define ABUF (128 * ASTRIDE * 2)   // bytes per buffer (34816)
__global__ __launch_bounds__(256) void gemm_mma(
    const __nv_bfloat16* __restrict__ Ahi, const __nv_bfloat16* __restrict__ Alo,
    const __nv_bfloat16* __restrict__ Bhi, const __nv_bfloat16* __restrict__ Blo,
    const float* __restrict__ bias,
    float* __restrict__ Cf, __nv_bfloat16* __restrict__ Chi, __nv_bfloat16* __restrict__ Clo,
    int M, int ncols, int act)
{
    extern __shared__ char sm[];
    char* AH = sm;
    char* AL = sm + ABUF;
    char* BH = sm + 2 * ABUF;
    char* BL = sm + 3 * ABUF;

    const int tid = threadIdx.x;
    const int warp = tid >> 5, lane = tid & 31;
    const int wm = warp >> 1, wn = warp & 1;
    const int rowBase = blockIdx.x * 128;
    const int colBase = blockIdx.y * 128;

    // ---- stage A/B (full K=128) ----
#pragma unroll
    for (int it = 0; it < 8; it++) {
        int idx = tid + it * 256;          // 0..2047
        int row = idx >> 4, kc = idx & 15;
        int gr = rowBase + row; if (gr >= M) gr = M - 1;
        int so = (row * ASTRIDE + kc * 8) * 2;
        *(uint4*)(AH + so) = *(const uint4*)(Ahi + (size_t)gr * 128 + kc * 8);
        *(uint4*)(AL + so) = *(const uint4*)(Alo + (size_t)gr * 128 + kc * 8);
        int gn = colBase + row;
        *(uint4*)(BH + so) = *(const uint4*)(Bhi + (size_t)gn * 128 + kc * 8);
        *(uint4*)(BL + so) = *(const uint4*)(Blo + (size_t)gn * 128 + kc * 8);
    }
    __syncthreads();

    const uint32_t ah_base = smem_u32(AH);
    const uint32_t al_base = smem_u32(AL);
    const uint32_t bh_base = smem_u32(BH);
    const uint32_t bl_base = smem_u32(BL);

    float acc[2][8][4];
#pragma unroll
    for (int i = 0; i < 2; i++)
#pragma unroll
        for (int j = 0; j < 8; j++)
#pragma unroll
            for (int k = 0; k < 4; k++) acc[i][j][k] = 0.f;

    // ldmatrix per-thread row offsets
    const int a_r = (lane & 15);            // row within 16-row tile
    const int a_c = (lane >> 4) * 8;        // k offset 0/8
    const int b_r = (lane & 7) + ((lane >> 4) << 3);   // n row within 16
    const int b_c = ((lane >> 3) & 1) * 8;  // k offset 0/8

#pragma unroll
    for (int kt = 0; kt < 8; kt++) {
        const int k0 = kt * 16;
        uint32_t ah[2][4], al[2][4];
#pragma unroll
        for (int mt = 0; mt < 2; mt++) {
            uint32_t off = ((wm * 32 + mt * 16 + a_r) * ASTRIDE + k0 + a_c) * 2;
            ldsm4(ah[mt][0], ah[mt][1], ah[mt][2], ah[mt][3], ah_base + off);
            ldsm4(al[mt][0], al[mt][1], al[mt][2], al[mt][3], al_base + off);
        }
        uint32_t bh[8][2], bl[8][2];
#pragma unroll
        for (int ng = 0; ng < 4; ng++) {    // n16 groups covering wn*64..+64
            uint32_t off = ((wn * 64 + ng * 16 + b_r) * ASTRIDE + k0 + b_c) * 2;
            ldsm4(bh[2 * ng][0], bh[2 * ng][1], bh[2 * ng + 1][0], bh[2 * ng + 1][1], bh_base + off);
            ldsm4(bl[2 * ng][0], bl[2 * ng][1], bl[2 * ng + 1][0], bl[2 * ng + 1][1], bl_base + off);
        }
#pragma unroll
        for (int mt = 0; mt < 2; mt++)
#pragma unroll
            for (int nt = 0; nt < 8; nt++) {
                mma_bf16(acc[mt][nt], ah[mt], bh[nt]);
                mma_bf16(acc[mt][nt], al[mt], bh[nt]);
                mma_bf16(acc[mt][nt], ah[mt], bl[nt]);
            }
    }

    // ---- epilogue ----
#pragma unroll
    for (int mt = 0; mt < 2; mt++) {
#pragma unroll
        for (int nt = 0; nt < 8; nt++) {
            int c = colBase + wn * 64 + nt * 8 + (lane & 3) * 2;
            float b0 = bias[c], b1 = bias[c + 1];
#pragma unroll
            for (int h = 0; h < 2; h++) {
                int r = rowBase + wm * 32 + mt * 16 + (lane >> 2) + h * 8;
                if (r < M) {
                    float v0 = acc[mt][nt][2 * h + 0] + b0;
                    float v1 = acc[mt][nt][2 * h + 1] + b1;
                    if (act) { v0 = gelu_f(v0); v1 = gelu_f(v1); }
                    if (Cf) {
                        *(float2*)(Cf + (size_t)r * ncols + c) = make_float2(v0, v1);
                    } else {
                        __nv_bfloat16 h0, l0, h1, l1;
                        split_bf16(v0, h0, l0);
                        split_bf16(v1, h1, l1);
                        __nv_bfloat162 hh; hh.x = h0; hh.y = h1;
                        __nv_bfloat162 ll; ll.x = l0; ll.y = l1;
                        *(__nv_bfloat162*)(Chi + (size_t)r * ncols + c) = hh;
                        *(__nv_bfloat162*)(Clo + (size_t)r * ncols + c) = ll;
                    }
                }
            }
        }
    }
}

// ---------------- edge kernels: one warp per dst node, fused softmax-agg ----
// layer1: qp stride 256 (q at +0, p at +128); emits m2 = gelu(h1+bg) as bf16 hi/lo
__global__ __launch_bounds__(256) void edge128_k(
    const float* __restrict__ qp, const float* __restrict__ a,
    const float* __restrict__ bg)
{
    int gw = (blockIdx.x * 256 + threadIdx.x) >> 5;
    if (gw >= NN) return;
    int lane = threadIdx.x & 31;
    int c = lane * 4;
    float4 qv = *(const float4*)(qp + (size_t)gw * 256 + c);
    float4 av = *(const float4*)(a + c);
    float ax = 0.f, ay = 0.f, az = 0.f, aw = 0.f;
    float denom = 0.f;
    int i = g_rowptr[gw];
    int end = g_rowptr[gw + 1];
    if (i < end) {
        int s = g_esrc[i];
        float4 pv = *(const float4*)(qp + (size_t)s * 256 + 128 + c);
        while (1) {
            float4 pvn;
            if (i + 1 < end) {
                int sn = g_esrc[i + 1];
                pvn = *(const float4*)(qp + (size_t)sn * 256 + 128 + c);
            }
            float tx = qv.x + pv.x; tx = tx > 0.f ? tx : 0.2f * tx;
            float ty = qv.y + pv.y; ty = ty > 0.f ? ty : 0.2f * ty;
            float tz = qv.z + pv.z; tz = tz > 0.f ? tz : 0.2f * tz;
            float tw = qv.w + pv.w; tw = tw > 0.f ? tw : 0.2f * tw;
            float part = fmaf(tx, av.x, fmaf(ty, av.y, fmaf(tz, av.z, tw * av.w)));
#pragma unroll
            for (int off = 16; off > 0; off >>= 1)
                part += __shfl_xor_sync(0xffffffffu, part, off);
            float es = __expf(part);
            denom += es;
            ax = fmaf(es, pv.x, ax);
            ay = fmaf(es, pv.y, ay);
            az = fmaf(es, pv.z, az);
            aw = fmaf(es, pv.w, aw);
            i++;
            if (i >= end) break;
            pv = pvn;
        }
    }
    float inv = denom > 0.f ? 1.0f / denom : 0.f;
    float4 bv = *(const float4*)(bg + c);
    float o[4];
    o[0] = gelu_f(fmaf(ax, inv, bv.x));
    o[1] = gelu_f(fmaf(ay, inv, bv.y));
    o[2] = gelu_f(fmaf(az, inv, bv.z));
    o[3] = gelu_f(fmaf(aw, inv, bv.w));
    __nv_bfloat16 h[4], l[4];
#pragma unroll
    for (int j = 0; j < 4; j++) split_bf16(o[j], h[j], l[j]);
    __nv_bfloat162 hh0; hh0.x = h[0]; hh0.y = h[1];
    __nv_bfloat162 hh1; hh1.x = h[2]; hh1.y = h[3];
    __nv_bfloat162 ll0; ll0.x = l[0]; ll0.y = l[1];
    __nv_bfloat162 ll1; ll1.x = l[2]; ll1.y = l[3];
    *(__nv_bfloat162*)(g_m2hi + (size_t)gw * 128 + c) = hh0;
    *(__nv_bfloat162*)(g_m2hi + (size_t)gw * 128 + c + 2) = hh1;
    *(__nv_bfloat162*)(g_m2lo + (size_t)gw * 128 + c) = ll0;
    *(__nv_bfloat162*)(g_m2lo + (size_t)gw * 128 + c + 2) = ll1;
}

// layer2: qp stride 128 (q at +0, p at +64); out = h2 + b_out
__global__ __launch_bounds__(256) void edge64_k(
    const float* __restrict__ qp, const float* __restrict__ a,
    const float* __restrict__ bo, float* __restrict__ out)
{
    int gw = (blockIdx.x * 256 + threadIdx.x) >> 5;
    if (gw >= NN) return;
    int lane = threadIdx.x & 31;
    int c = lane * 2;
    float2 qv = *(const float2*)(qp + (size_t)gw * 128 + c);
    float2 av = *(const float2*)(a + c);
    float ax = 0.f, ay = 0.f;
    float denom = 0.f;
    int i = g_rowptr[gw];
    int end = g_rowptr[gw + 1];
    if (i < end) {
        int s = g_esrc[i];
        float2 pv = *(const float2*)(qp + (size_t)s * 128 + 64 + c);
        while (1) {
            float2 pvn;
            if (i + 1 < end) {
                int sn = g_esrc[i + 1];
                pvn = *(const float2*)(qp + (size_t)sn * 128 + 64 + c);
            }
            float tx = qv.x + pv.x; tx = tx > 0.f ? tx : 0.2f * tx;
            float ty = qv.y + pv.y; ty = ty > 0.f ? ty : 0.2f * ty;
            float part = fmaf(tx, av.x, ty * av.y);
#pragma unroll
            for (int off = 16; off > 0; off >>= 1)
                part += __shfl_xor_sync(0xffffffffu, part, off);
            float es = __expf(part);
            denom += es;
            ax = fmaf(es, pv.x, ax);
            ay = fmaf(es, pv.y, ay);
            i++;
            if (i >= end) break;
            pv = pvn;
        }
    }
    float inv = denom > 0.f ? 1.0f / denom : 0.f;
    float2 bv = *(const float2*)(bo + c);
    float2 o;
    o.x = fmaf(ax, inv, bv.x);
    o.y = fmaf(ay, inv, bv.y);
    *(float2*)(out + (size_t)gw * 64 + c) = o;
}

// ---------------- launch ----------------
extern "C" void kernel_launch(void* const* d_in, const int* in_sizes, int n_in,
                              void* d_out, int out_size)
{
    const float* x    = (const float*)d_in[0];
    const float* W0   = (const float*)d_in[1];
    const float* b0   = (const float*)d_in[2];
    const float* Wq1  = (const float*)d_in[3];
    const float* bq1  = (const float*)d_in[4];
    const float* Wp1  = (const float*)d_in[5];
    const float* bp1  = (const float*)d_in[6];
    const float* a1   = (const float*)d_in[7];
    const float* bg2  = (const float*)d_in[8];
    const float* Wq2  = (const float*)d_in[9];
    const float* bq2  = (const float*)d_in[10];
    const float* Wp2  = (const float*)d_in[11];
    const float* bp2  = (const float*)d_in[12];
    const float* a2   = (const float*)d_in[13];
    const float* bout = (const float*)d_in[14];
    const int*   src  = (const int*)d_in[15];
    const int*   dst  = (const int*)d_in[16];
    float* out = (float*)d_out;

    __nv_bfloat16 *xhi, *xlo, *m1hi, *m1lo, *m2hi, *m2lo;
    __nv_bfloat16 *w0h, *w0l, *wqp1h, *wqp1l, *wqp2h, *wqp2l;
    float *qp1, *qp2, *bqp1, *bqp2;
    cudaGetSymbolAddress((void**)&xhi, g_xhi);   cudaGetSymbolAddress((void**)&xlo, g_xlo);
    cudaGetSymbolAddress((void**)&m1hi, g_m1hi); cudaGetSymbolAddress((void**)&m1lo, g_m1lo);
    cudaGetSymbolAddress((void**)&m2hi, g_m2hi); cudaGetSymbolAddress((void**)&m2lo, g_m2lo);
    cudaGetSymbolAddress((void**)&w0h, g_w0t_hi);    cudaGetSymbolAddress((void**)&w0l, g_w0t_lo);
    cudaGetSymbolAddress((void**)&wqp1h, g_wqp1t_hi); cudaGetSymbolAddress((void**)&wqp1l, g_wqp1t_lo);
    cudaGetSymbolAddress((void**)&wqp2h, g_wqp2t_hi); cudaGetSymbolAddress((void**)&wqp2l, g_wqp2t_lo);
    cudaGetSymbolAddress((void**)&qp1, g_qp1); cudaGetSymbolAddress((void**)&qp2, g_qp2);
    cudaGetSymbolAddress((void**)&bqp1, g_bqp1); cudaGetSymbolAddress((void**)&bqp2, g_bqp2);

    constexpr int SMEM = 4 * ABUF;   // 139264 B
    static int attr_set = 0;
    cudaFuncSetAttribute(gemm_mma, cudaFuncAttributeMaxDynamicSharedMemorySize, SMEM);
    (void)attr_set;

    // CSR build
    zero_k<<<(NN + 255) / 256, 256>>>();
    hist_k<<<(EE + 255) / 256, 256>>>(dst);
    scan_k<<<1, 1024>>>();
    scatter_k<<<(EE + 255) / 256, 256>>>(src, dst);

    // conversions (hoisted hi/lo splits; transposed weights)
    convx_k<<<(NN * 128 + 255) / 256, 256>>>(x);
    convw_k<<<(128 * 128 + 255) / 256, 256>>>(W0, W0, b0, b0, w0h, w0l, nullptr, 128, 0);
    convw_k<<<(256 * 128 + 255) / 256, 256>>>(Wq1, Wp1, bq1, bp1, wqp1h, wqp1l, bqp1, 128, 128);
    convw_k<<<(128 * 128 + 255) / 256, 256>>>(Wq2, Wp2, bq2, bp2, wqp2h, wqp2l, bqp2, 64, 64);

    const int MB = (NN + 127) / 128;

    // layer 1
    gemm_mma<<<dim3(MB, 1), 256, SMEM>>>(xhi, xlo, w0h, w0l, b0,
                                         nullptr, m1hi, m1lo, NN, 128, 1);   // m1 (bf16 hi/lo)
    gemm_mma<<<dim3(MB, 2), 256, SMEM>>>(m1hi, m1lo, wqp1h, wqp1l, bqp1,
                                         qp1, nullptr, nullptr, NN, 256, 0); // q1|p1
    edge128_k<<<(NN * 32 + 255) / 256, 256>>>(qp1, a1, bg2);                 // m2 (bf16 hi/lo)

    // layer 2
    gemm_mma<<<dim3(MB, 1), 256, SMEM>>>(m2hi, m2lo, wqp2h, wqp2l, bqp2,
                                         qp2, nullptr, nullptr, NN, 128, 0); // q2|p2
    edge64_k<<<(NN * 32 + 255) / 256, 256>>>(qp2, a2, bout, out);            // out
}

// round 6
// speedup vs baseline: 2.2772x; 1.1017x over previous
#include <cuda_runtime.h>
#include <cuda_fp16.h>
#include <cstdint>

#define NN 50000
#define EE 800000

// ---------------- scratch (static device globals; no allocs) ----------------
__device__ __half g_xhi[NN * 128],  g_xlo[NN * 128];
__device__ __half g_m1hi[NN * 128], g_m1lo[NN * 128];
__device__ __half g_m2hi[NN * 128], g_m2lo[NN * 128];
__device__ float g_qp1[NN * 256];   // [node][0:128]=q1, [128:256]=p1
__device__ float g_qp2[NN * 128];   // [node][0:64]=q2, [64:128]=p2
// transposed weights: Wt[n][k] = W[k][n], fp16 (hi only; activation side is split)
__device__ __half g_w0t[128 * 128];
__device__ __half g_wqp1t[256 * 128];
__device__ __half g_wqp2t[128 * 128];
__device__ float g_bqp1[256];
__device__ float g_bqp2[128];
__device__ int   g_rowptr[NN + 1];
__device__ int   g_cursor[NN];
__device__ int   g_esrc[EE];

__device__ __forceinline__ float gelu_f(float x) {
    return 0.5f * x * (1.0f + erff(x * 0.70710678118654752440f));
}
__device__ __forceinline__ void split_h(float v, __half& hi, __half& lo) {
    hi = __float2half_rn(v);
    lo = __float2half_rn(v - __half2float(hi));
}
__device__ __forceinline__ uint32_t smem_u32(const void* p) {
    uint32_t a;
    asm("{ .reg .u64 t; cvta.to.shared.u64 t, %1; cvt.u32.u64 %0, t; }" : "=r"(a) : "l"(p));
    return a;
}
__device__ __forceinline__ void ldsm4(uint32_t& r0, uint32_t& r1, uint32_t& r2, uint32_t& r3, uint32_t addr) {
    asm volatile("ldmatrix.sync.aligned.m8n8.x4.shared.b16 {%0,%1,%2,%3}, [%4];"
                 : "=r"(r0), "=r"(r1), "=r"(r2), "=r"(r3) : "r"(addr));
}
__device__ __forceinline__ void mma_f16(float* c, const uint32_t* a, const uint32_t* b) {
    asm volatile(
        "mma.sync.aligned.m16n8k16.row.col.f32.f16.f16.f32 "
        "{%0,%1,%2,%3}, {%4,%5,%6,%7}, {%8,%9}, {%0,%1,%2,%3};"
        : "+f"(c[0]), "+f"(c[1]), "+f"(c[2]), "+f"(c[3])
        : "r"(a[0]), "r"(a[1]), "r"(a[2]), "r"(a[3]), "r"(b[0]), "r"(b[1]));
}
__device__ __forceinline__ void cp16(uint32_t saddr, const void* gaddr) {
    asm volatile("cp.async.cg.shared.global [%0], [%1], 16;" :: "r"(saddr), "l"(gaddr) : "memory");
}

// ---------------- CSR build ----------------
__global__ void zero_k() {
    int i = blockIdx.x * blockDim.x + threadIdx.x;
    if (i < NN) g_cursor[i] = 0;
}
__global__ void hist_k(const int* __restrict__ dst) {
    int e = blockIdx.x * blockDim.x + threadIdx.x;
    if (e < EE) atomicAdd(&g_cursor[dst[e]], 1);
}
__global__ __launch_bounds__(1024) void scan_k() {
    __shared__ int warpsum[32];
    __shared__ int s_carry;
    __shared__ int s_tot;
    int tid = threadIdx.x, lane = tid & 31, wid = tid >> 5;
    if (tid == 0) s_carry = 0;
    __syncthreads();
    for (int base = 0; base < NN; base += 8192) {
        int idx0 = base + tid * 8;
        int v[8]; int tot = 0;
#pragma unroll
        for (int j = 0; j < 8; j++) {
            int id = idx0 + j;
            v[j] = (id < NN) ? g_cursor[id] : 0;
            tot += v[j];
        }
        int incl = tot;
#pragma unroll
        for (int off = 1; off < 32; off <<= 1) {
            int t = __shfl_up_sync(0xffffffffu, incl, off);
            if (lane >= off) incl += t;
        }
        if (lane == 31) warpsum[wid] = incl;
        __syncthreads();
        if (wid == 0) {
            int w = warpsum[lane];
            int wi = w;
#pragma unroll
            for (int off = 1; off < 32; off <<= 1) {
                int t = __shfl_up_sync(0xffffffffu, wi, off);
                if (lane >= off) wi += t;
            }
            warpsum[lane] = wi - w;
            if (lane == 31) s_tot = wi;
        }
        __syncthreads();
        int run = s_carry + warpsum[wid] + (incl - tot);
#pragma unroll
        for (int j = 0; j < 8; j++) {
            int id = idx0 + j;
            if (id < NN) { g_rowptr[id] = run; g_cursor[id] = 0; }
            run += v[j];
        }
        __syncthreads();
        if (tid == 0) s_carry += s_tot;
        __syncthreads();
    }
    if (threadIdx.x == 0) g_rowptr[NN] = s_carry;
}
__global__ void scatter_k(const int* __restrict__ src, const int* __restrict__ dst) {
    int e = blockIdx.x * blockDim.x + threadIdx.x;
    if (e < EE) {
        int d = dst[e];
        int pos = g_rowptr[d] + atomicAdd(&g_cursor[d], 1);
        g_esrc[pos] = src[e];
    }
}

// ---------------- conversions ----------------
__global__ void convx_k(const float* __restrict__ x) {
    int i = blockIdx.x * blockDim.x + threadIdx.x;
    if (i < NN * 128) {
        __half h, l;
        split_h(x[i], h, l);
        g_xhi[i] = h; g_xlo[i] = l;
    }
}
// Wt[n][k] = (n<na ? Wa[k][n] : Wb[k][n-na]) as fp16; concat biases
__global__ void convw_k(const float* __restrict__ Wa, const float* __restrict__ Wb,
                        const float* __restrict__ ba, const float* __restrict__ bb,
                        __half* __restrict__ Wt, float* __restrict__ bc, int na, int nb) {
    int nc = na + nb;
    int i = blockIdx.x * blockDim.x + threadIdx.x;
    if (i < nc * 128) {
        int n = i >> 7, k = i & 127;
        float v = (n < na) ? Wa[(size_t)k * na + n] : Wb[(size_t)k * nb + (n - na)];
        Wt[i] = __float2half_rn(v);
    }
    if (bc && i < nc) bc[i] = (i < na) ? ba[i] : bb[i - na];
}

// ---------------- fp16 x2-split mma.sync GEMM, cp.async pipelined ------------
// C[M, ncols] = act((Ah+Al)[M,128] @ Wt^T + bias). BM=128, BN=128, K=128.
// 256 threads = 8 warps (wm 0..3, wn 0..1), warp tile 32x64.
#define ASTRIDE 136
#define ABUF (128 * ASTRIDE * 2)   // 34816 B per buffer
__global__ __launch_bounds__(256, 2) void gemm_mma(
    const __half* __restrict__ Ahi, const __half* __restrict__ Alo,
    const __half* __restrict__ Bh, const float* __restrict__ bias,
    float* __restrict__ Cf, __half* __restrict__ Chi, __half* __restrict__ Clo,
    int M, int ncols, int act)
{
    extern __shared__ char sm[];
    char* AH = sm;
    char* AL = sm + ABUF;
    char* BH = sm + 2 * ABUF;

    const int tid = threadIdx.x;
    const int warp = tid >> 5, lane = tid & 31;
    const int wm = warp >> 1, wn = warp & 1;
    const int rowBase = blockIdx.x * 128;
    const int colBase = blockIdx.y * 128;

    const uint32_t ah_base = smem_u32(AH);
    const uint32_t al_base = smem_u32(AL);
    const uint32_t bh_base = smem_u32(BH);

    // ---- async staging: two commit groups (k<64, k>=64) ----
#pragma unroll
    for (int g = 0; g < 2; g++) {
#pragma unroll
        for (int it = 0; it < 4; it++) {
            int idx = tid + it * 256;               // 0..1023
            int row = idx >> 3, ch = (idx & 7) + g * 8;
            int gr = rowBase + row; if (gr >= M) gr = M - 1;
            uint32_t so = (uint32_t)(row * ASTRIDE + ch * 8) * 2;
            cp16(ah_base + so, Ahi + (size_t)gr * 128 + ch * 8);
            cp16(al_base + so, Alo + (size_t)gr * 128 + ch * 8);
            int gn = colBase + row;
            cp16(bh_base + so, Bh + (size_t)gn * 128 + ch * 8);
        }
        asm volatile("cp.async.commit_group;" ::: "memory");
    }

    float acc[2][8][4];
#pragma unroll
    for (int i = 0; i < 2; i++)
#pragma unroll
        for (int j = 0; j < 8; j++)
#pragma unroll
            for (int k = 0; k < 4; k++) acc[i][j][k] = 0.f;

    const int a_r = (lane & 15);
    const int a_c = (lane >> 4) * 8;
    const int b_r = (lane & 7) + ((lane >> 4) << 3);
    const int b_c = ((lane >> 3) & 1) * 8;

#pragma unroll
    for (int half = 0; half < 2; half++) {
        if (half == 0) asm volatile("cp.async.wait_group 1;" ::: "memory");
        else           asm volatile("cp.async.wait_group 0;" ::: "memory");
        __syncthreads();
#pragma unroll
        for (int ks = 0; ks < 4; ks++) {
            const int k0 = half * 64 + ks * 16;
            uint32_t ah[2][4], al[2][4];
#pragma unroll
            for (int mt = 0; mt < 2; mt++) {
                uint32_t off = (uint32_t)((wm * 32 + mt * 16 + a_r) * ASTRIDE + k0 + a_c) * 2;
                ldsm4(ah[mt][0], ah[mt][1], ah[mt][2], ah[mt][3], ah_base + off);
                ldsm4(al[mt][0], al[mt][1], al[mt][2], al[mt][3], al_base + off);
            }
            uint32_t bh[8][2];
#pragma unroll
            for (int ng = 0; ng < 4; ng++) {
                uint32_t off = (uint32_t)((wn * 64 + ng * 16 + b_r) * ASTRIDE + k0 + b_c) * 2;
                ldsm4(bh[2 * ng][0], bh[2 * ng][1], bh[2 * ng + 1][0], bh[2 * ng + 1][1], bh_base + off);
            }
#pragma unroll
            for (int mt = 0; mt < 2; mt++)
#pragma unroll
                for (int nt = 0; nt < 8; nt++) {
                    mma_f16(acc[mt][nt], ah[mt], bh[nt]);
                    mma_f16(acc[mt][nt], al[mt], bh[nt]);
                }
        }
    }

    // ---- epilogue ----
#pragma unroll
    for (int mt = 0; mt < 2; mt++) {
#pragma unroll
        for (int nt = 0; nt < 8; nt++) {
            int c = colBase + wn * 64 + nt * 8 + (lane & 3) * 2;
            float b0 = bias[c], b1 = bias[c + 1];
#pragma unroll
            for (int h = 0; h < 2; h++) {
                int r = rowBase + wm * 32 + mt * 16 + (lane >> 2) + h * 8;
                if (r < M) {
                    float v0 = acc[mt][nt][2 * h + 0] + b0;
                    float v1 = acc[mt][nt][2 * h + 1] + b1;
                    if (act) { v0 = gelu_f(v0); v1 = gelu_f(v1); }
                    if (Cf) {
                        *(float2*)(Cf + (size_t)r * ncols + c) = make_float2(v0, v1);
                    } else {
                        __half h0, l0, h1, l1;
                        split_h(v0, h0, l0);
                        split_h(v1, h1, l1);
                        __half2 hh; hh.x = h0; hh.y = h1;
                        __half2 ll; ll.x = l0; ll.y = l1;
                        *(__half2*)(Chi + (size_t)r * ncols + c) = hh;
                        *(__half2*)(Clo + (size_t)r * ncols + c) = ll;
                    }
                }
            }
        }
    }
}

// ---------------- edge kernels: one warp per dst node, fused softmax-agg ----
// layer1: qp stride 256 (q at +0, p at +128); emits m2 = gelu(h1+bg) as fp16 hi/lo
__global__ __launch_bounds__(256) void edge128_k(
    const float* __restrict__ qp, const float* __restrict__ a,
    const float* __restrict__ bg)
{
    int gw = (blockIdx.x * 256 + threadIdx.x) >> 5;
    if (gw >= NN) return;
    int lane = threadIdx.x & 31;
    int c = lane * 4;
    float4 qv = *(const float4*)(qp + (size_t)gw * 256 + c);
    float4 av = *(const float4*)(a + c);
    float ax = 0.f, ay = 0.f, az = 0.f, aw = 0.f;
    float denom = 0.f;
    int i = g_rowptr[gw];
    int end = g_rowptr[gw + 1];
    if (i < end) {
        int s = g_esrc[i];
        float4 pv = *(const float4*)(qp + (size_t)s * 256 + 128 + c);
        while (1) {
            float4 pvn;
            if (i + 1 < end) {
                int sn = g_esrc[i + 1];
                pvn = *(const float4*)(qp + (size_t)sn * 256 + 128 + c);
            }
            float tx = qv.x + pv.x; tx = tx > 0.f ? tx : 0.2f * tx;
            float ty = qv.y + pv.y; ty = ty > 0.f ? ty : 0.2f * ty;
            float tz = qv.z + pv.z; tz = tz > 0.f ? tz : 0.2f * tz;
            float tw = qv.w + pv.w; tw = tw > 0.f ? tw : 0.2f * tw;
            float part = fmaf(tx, av.x, fmaf(ty, av.y, fmaf(tz, av.z, tw * av.w)));
#pragma unroll
            for (int off = 16; off > 0; off >>= 1)
                part += __shfl_xor_sync(0xffffffffu, part, off);
            float es = __expf(part);
            denom += es;
            ax = fmaf(es, pv.x, ax);
            ay = fmaf(es, pv.y, ay);
            az = fmaf(es, pv.z, az);
            aw = fmaf(es, pv.w, aw);
            i++;
            if (i >= end) break;
            pv = pvn;
        }
    }
    float inv = denom > 0.f ? 1.0f / denom : 0.f;
    float4 bv = *(const float4*)(bg + c);
    float o[4];
    o[0] = gelu_f(fmaf(ax, inv, bv.x));
    o[1] = gelu_f(fmaf(ay, inv, bv.y));
    o[2] = gelu_f(fmaf(az, inv, bv.z));
    o[3] = gelu_f(fmaf(aw, inv, bv.w));
    __half h[4], l[4];
#pragma unroll
    for (int j = 0; j < 4; j++) split_h(o[j], h[j], l[j]);
    __half2 hh0; hh0.x = h[0]; hh0.y = h[1];
    __half2 hh1; hh1.x = h[2]; hh1.y = h[3];
    __half2 ll0; ll0.x = l[0]; ll0.y = l[1];
    __half2 ll1; ll1.x = l[2]; ll1.y = l[3];
    *(__half2*)(g_m2hi + (size_t)gw * 128 + c) = hh0;
    *(__half2*)(g_m2hi + (size_t)gw * 128 + c + 2) = hh1;
    *(__half2*)(g_m2lo + (size_t)gw * 128 + c) = ll0;
    *(__half2*)(g_m2lo + (size_t)gw * 128 + c + 2) = ll1;
}

// layer2: qp stride 128 (q at +0, p at +64); out = h2 + b_out
__global__ __launch_bounds__(256) void edge64_k(
    const float* __restrict__ qp, const float* __restrict__ a,
    const float* __restrict__ bo, float* __restrict__ out)
{
    int gw = (blockIdx.x * 256 + threadIdx.x) >> 5;
    if (gw >= NN) return;
    int lane = threadIdx.x & 31;
    int c = lane * 2;
    float2 qv = *(const float2*)(qp + (size_t)gw * 128 + c);
    float2 av = *(const float2*)(a + c);
    float ax = 0.f, ay = 0.f;
    float denom = 0.f;
    int i = g_rowptr[gw];
    int end = g_rowptr[gw + 1];
    if (i < end) {
        int s = g_esrc[i];
        float2 pv = *(const float2*)(qp + (size_t)s * 128 + 64 + c);
        while (1) {
            float2 pvn;
            if (i + 1 < end) {
                int sn = g_esrc[i + 1];
                pvn = *(const float2*)(qp + (size_t)sn * 128 + 64 + c);
            }
            float tx = qv.x + pv.x; tx = tx > 0.f ? tx : 0.2f * tx;
            float ty = qv.y + pv.y; ty = ty > 0.f ? ty : 0.2f * ty;
            float part = fmaf(tx, av.x, ty * av.y);
#pragma unroll
            for (int off = 16; off > 0; off >>= 1)
                part += __shfl_xor_sync(0xffffffffu, part, off);
            float es = __expf(part);
            denom += es;
            ax = fmaf(es, pv.x, ax);
            ay = fmaf(es, pv.y, ay);
            i++;
            if (i >= end) break;
            pv = pvn;
        }
    }
    float inv = denom > 0.f ? 1.0f / denom : 0.f;
    float2 bv = *(const float2*)(bo + c);
    float2 o;
    o.x = fmaf(ax, inv, bv.x);
    o.y = fmaf(ay, inv, bv.y);
    *(float2*)(out + (size_t)gw * 64 + c) = o;
}

// ---------------- launch ----------------
extern "C" void kernel_launch(void* const* d_in, const int* in_sizes, int n_in,
                              void* d_out, int out_size)
{
    const float* x    = (const float*)d_in[0];
    const float* W0   = (const float*)d_in[1];
    const float* b0   = (const float*)d_in[2];
    const float* Wq1  = (const float*)d_in[3];
    const float* bq1  = (const float*)d_in[4];
    const float* Wp1  = (const float*)d_in[5];
    const float* bp1  = (const float*)d_in[6];
    const float* a1   = (const float*)d_in[7];
    const float* bg2  = (const float*)d_in[8];
    const float* Wq2  = (const float*)d_in[9];
    const float* bq2  = (const float*)d_in[10];
    const float* Wp2  = (const float*)d_in[11];
    const float* bp2  = (const float*)d_in[12];
    const float* a2   = (const float*)d_in[13];
    const float* bout = (const float*)d_in[14];
    const int*   src  = (const int*)d_in[15];
    const int*   dst  = (const int*)d_in[16];
    float* out = (float*)d_out;

    __half *xhi, *xlo, *m1hi, *m1lo, *m2hi, *m2lo, *w0t, *wqp1t, *wqp2t;
    float *qp1, *qp2, *bqp1, *bqp2;
    cudaGetSymbolAddress((void**)&xhi, g_xhi);   cudaGetSymbolAddress((void**)&xlo, g_xlo);
    cudaGetSymbolAddress((void**)&m1hi, g_m1hi); cudaGetSymbolAddress((void**)&m1lo, g_m1lo);
    cudaGetSymbolAddress((void**)&m2hi, g_m2hi); cudaGetSymbolAddress((void**)&m2lo, g_m2lo);
    cudaGetSymbolAddress((void**)&w0t, g_w0t);
    cudaGetSymbolAddress((void**)&wqp1t, g_wqp1t);
    cudaGetSymbolAddress((void**)&wqp2t, g_wqp2t);
    cudaGetSymbolAddress((void**)&qp1, g_qp1); cudaGetSymbolAddress((void**)&qp2, g_qp2);
    cudaGetSymbolAddress((void**)&bqp1, g_bqp1); cudaGetSymbolAddress((void**)&bqp2, g_bqp2);

    constexpr int SMEM = 3 * ABUF;   // 104448 B
    cudaFuncSetAttribute(gemm_mma, cudaFuncAttributeMaxDynamicSharedMemorySize, SMEM);

    // CSR build
    zero_k<<<(NN + 255) / 256, 256>>>();
    hist_k<<<(EE + 255) / 256, 256>>>(dst);
    scan_k<<<1, 1024>>>();
    scatter_k<<<(EE + 255) / 256, 256>>>(src, dst);

    // conversions
    convx_k<<<(NN * 128 + 255) / 256, 256>>>(x);
    convw_k<<<(128 * 128 + 255) / 256, 256>>>(W0, W0, b0, b0, w0t, nullptr, 128, 0);
    convw_k<<<(256 * 128 + 255) / 256, 256>>>(Wq1, Wp1, bq1, bp1, wqp1t, bqp1, 128, 128);
    convw_k<<<(128 * 128 + 255) / 256, 256>>>(Wq2, Wp2, bq2, bp2, wqp2t, bqp2, 64, 64);

    const int MB = (NN + 127) / 128;

    // layer 1
    gemm_mma<<<dim3(MB, 1), 256, SMEM>>>(xhi, xlo, w0t, b0,
                                         nullptr, m1hi, m1lo, NN, 128, 1);   // m1 (fp16 hi/lo)
    gemm_mma<<<dim3(MB, 2), 256, SMEM>>>(m1hi, m1lo, wqp1t, bqp1,
                                         qp1, nullptr, nullptr, NN, 256, 0); // q1|p1
    edge128_k<<<(NN * 32 + 255) / 256, 256>>>(qp1, a1, bg2);                 // m2 (fp16 hi/lo)

    // layer 2
    gemm_mma<<<dim3(MB, 1), 256, SMEM>>>(m2hi, m2lo, wqp2t, bqp2,
                                         qp2, nullptr, nullptr, NN, 128, 0); // q2|p2
    edge64_k<<<(NN * 32 + 255) / 256, 256>>>(qp2, a2, bout, out);            // out
}

// round 7
// speedup vs baseline: 2.8519x; 1.2524x over previous
#include <cuda_runtime.h>
#include <cuda_fp16.h>
#include <cstdint>

#define NN 50000
#define EE 800000

// ---------------- scratch (static device globals; no allocs) ----------------
__device__ __half g_xhi[NN * 128],  g_xlo[NN * 128];
__device__ __half g_m1hi[NN * 128], g_m1lo[NN * 128];
__device__ __half g_m2hi[NN * 128], g_m2lo[NN * 128];
__device__ float g_qp1[NN * 256];   // [node][0:128]=q1, [128:256]=p1
__device__ float g_qp2[NN * 128];   // [node][0:64]=q2, [64:128]=p2
__device__ __half g_w0t[128 * 128];
__device__ __half g_wqp1t[256 * 128];
__device__ __half g_wqp2t[128 * 128];
__device__ float g_bqp1[256];
__device__ float g_bqp2[128];
__device__ int   g_rowptr[NN + 1];
__device__ int   g_cursor[NN];
__device__ int   g_esrc[EE];

__device__ __forceinline__ float gelu_f(float x) {
    return 0.5f * x * (1.0f + erff(x * 0.70710678118654752440f));
}
__device__ __forceinline__ void split_h(float v, __half& hi, __half& lo) {
    hi = __float2half_rn(v);
    lo = __float2half_rn(v - __half2float(hi));
}
__device__ __forceinline__ uint32_t smem_u32(const void* p) {
    uint32_t a;
    asm("{ .reg .u64 t; cvta.to.shared.u64 t, %1; cvt.u32.u64 %0, t; }" : "=r"(a) : "l"(p));
    return a;
}
__device__ __forceinline__ void ldsm4(uint32_t& r0, uint32_t& r1, uint32_t& r2, uint32_t& r3, uint32_t addr) {
    asm volatile("ldmatrix.sync.aligned.m8n8.x4.shared.b16 {%0,%1,%2,%3}, [%4];"
                 : "=r"(r0), "=r"(r1), "=r"(r2), "=r"(r3) : "r"(addr));
}
__device__ __forceinline__ void mma_f16(float* c, const uint32_t* a, const uint32_t* b) {
    asm volatile(
        "mma.sync.aligned.m16n8k16.row.col.f32.f16.f16.f32 "
        "{%0,%1,%2,%3}, {%4,%5,%6,%7}, {%8,%9}, {%0,%1,%2,%3};"
        : "+f"(c[0]), "+f"(c[1]), "+f"(c[2]), "+f"(c[3])
        : "r"(a[0]), "r"(a[1]), "r"(a[2]), "r"(a[3]), "r"(b[0]), "r"(b[1]));
}
__device__ __forceinline__ void cp16(uint32_t saddr, const void* gaddr) {
    asm volatile("cp.async.cg.shared.global [%0], [%1], 16;" :: "r"(saddr), "l"(gaddr) : "memory");
}

// ---------------- CSR build ----------------
__global__ void zero_k() {
    int i = blockIdx.x * blockDim.x + threadIdx.x;
    if (i < NN) g_cursor[i] = 0;
}
__global__ void hist_k(const int* __restrict__ dst) {
    int e = blockIdx.x * blockDim.x + threadIdx.x;
    if (e < EE) atomicAdd(&g_cursor[dst[e]], 1);
}
__global__ __launch_bounds__(1024) void scan_k() {
    __shared__ int warpsum[32];
    __shared__ int s_carry;
    __shared__ int s_tot;
    int tid = threadIdx.x, lane = tid & 31, wid = tid >> 5;
    if (tid == 0) s_carry = 0;
    __syncthreads();
    for (int base = 0; base < NN; base += 8192) {
        int idx0 = base + tid * 8;
        int v[8]; int tot = 0;
#pragma unroll
        for (int j = 0; j < 8; j++) {
            int id = idx0 + j;
            v[j] = (id < NN) ? g_cursor[id] : 0;
            tot += v[j];
        }
        int incl = tot;
#pragma unroll
        for (int off = 1; off < 32; off <<= 1) {
            int t = __shfl_up_sync(0xffffffffu, incl, off);
            if (lane >= off) incl += t;
        }
        if (lane == 31) warpsum[wid] = incl;
        __syncthreads();
        if (wid == 0) {
            int w = warpsum[lane];
            int wi = w;
#pragma unroll
            for (int off = 1; off < 32; off <<= 1) {
                int t = __shfl_up_sync(0xffffffffu, wi, off);
                if (lane >= off) wi += t;
            }
            warpsum[lane] = wi - w;
            if (lane == 31) s_tot = wi;
        }
        __syncthreads();
        int run = s_carry + warpsum[wid] + (incl - tot);
#pragma unroll
        for (int j = 0; j < 8; j++) {
            int id = idx0 + j;
            if (id < NN) { g_rowptr[id] = run; g_cursor[id] = 0; }
            run += v[j];
        }
        __syncthreads();
        if (tid == 0) s_carry += s_tot;
        __syncthreads();
    }
    if (threadIdx.x == 0) g_rowptr[NN] = s_carry;
}
__global__ void scatter_k(const int* __restrict__ src, const int* __restrict__ dst) {
    int e = blockIdx.x * blockDim.x + threadIdx.x;
    if (e < EE) {
        int d = dst[e];
        int pos = g_rowptr[d] + atomicAdd(&g_cursor[d], 1);
        g_esrc[pos] = src[e];
    }
}

// ---------------- conversions ----------------
__global__ void convx_k(const float* __restrict__ x) {
    int i = blockIdx.x * blockDim.x + threadIdx.x;
    if (i < NN * 128) {
        __half h, l;
        split_h(x[i], h, l);
        g_xhi[i] = h; g_xlo[i] = l;
    }
}
__global__ void convw_k(const float* __restrict__ Wa, const float* __restrict__ Wb,
                        const float* __restrict__ ba, const float* __restrict__ bb,
                        __half* __restrict__ Wt, float* __restrict__ bc, int na, int nb) {
    int nc = na + nb;
    int i = blockIdx.x * blockDim.x + threadIdx.x;
    if (i < nc * 128) {
        int n = i >> 7, k = i & 127;
        float v = (n < na) ? Wa[(size_t)k * na + n] : Wb[(size_t)k * nb + (n - na)];
        Wt[i] = __float2half_rn(v);
    }
    if (bc && i < nc) bc[i] = (i < na) ? ba[i] : bb[i - na];
}

// ---------------- fp16 x2-split mma.sync GEMM, cp.async pipelined ------------
#define ASTRIDE 136
#define ABUF (128 * ASTRIDE * 2)   // 34816 B per buffer
__global__ __launch_bounds__(256, 2) void gemm_mma(
    const __half* __restrict__ Ahi, const __half* __restrict__ Alo,
    const __half* __restrict__ Bh, const float* __restrict__ bias,
    float* __restrict__ Cf, __half* __restrict__ Chi, __half* __restrict__ Clo,
    int M, int ncols, int act)
{
    extern __shared__ char sm[];
    char* AH = sm;
    char* AL = sm + ABUF;
    char* BH = sm + 2 * ABUF;

    const int tid = threadIdx.x;
    const int warp = tid >> 5, lane = tid & 31;
    const int wm = warp >> 1, wn = warp & 1;
    const int rowBase = blockIdx.x * 128;
    const int colBase = blockIdx.y * 128;

    const uint32_t ah_base = smem_u32(AH);
    const uint32_t al_base = smem_u32(AL);
    const uint32_t bh_base = smem_u32(BH);

#pragma unroll
    for (int g = 0; g < 2; g++) {
#pragma unroll
        for (int it = 0; it < 4; it++) {
            int idx = tid + it * 256;
            int row = idx >> 3, ch = (idx & 7) + g * 8;
            int gr = rowBase + row; if (gr >= M) gr = M - 1;
            uint32_t so = (uint32_t)(row * ASTRIDE + ch * 8) * 2;
            cp16(ah_base + so, Ahi + (size_t)gr * 128 + ch * 8);
            cp16(al_base + so, Alo + (size_t)gr * 128 + ch * 8);
            int gn = colBase + row;
            cp16(bh_base + so, Bh + (size_t)gn * 128 + ch * 8);
        }
        asm volatile("cp.async.commit_group;" ::: "memory");
    }

    float acc[2][8][4];
#pragma unroll
    for (int i = 0; i < 2; i++)
#pragma unroll
        for (int j = 0; j < 8; j++)
#pragma unroll
            for (int k = 0; k < 4; k++) acc[i][j][k] = 0.f;

    const int a_r = (lane & 15);
    const int a_c = (lane >> 4) * 8;
    const int b_r = (lane & 7) + ((lane >> 4) << 3);
    const int b_c = ((lane >> 3) & 1) * 8;

#pragma unroll
    for (int half = 0; half < 2; half++) {
        if (half == 0) asm volatile("cp.async.wait_group 1;" ::: "memory");
        else           asm volatile("cp.async.wait_group 0;" ::: "memory");
        __syncthreads();
#pragma unroll
        for (int ks = 0; ks < 4; ks++) {
            const int k0 = half * 64 + ks * 16;
            uint32_t ah[2][4], al[2][4];
#pragma unroll
            for (int mt = 0; mt < 2; mt++) {
                uint32_t off = (uint32_t)((wm * 32 + mt * 16 + a_r) * ASTRIDE + k0 + a_c) * 2;
                ldsm4(ah[mt][0], ah[mt][1], ah[mt][2], ah[mt][3], ah_base + off);
                ldsm4(al[mt][0], al[mt][1], al[mt][2], al[mt][3], al_base + off);
            }
            uint32_t bh[8][2];
#pragma unroll
            for (int ng = 0; ng < 4; ng++) {
                uint32_t off = (uint32_t)((wn * 64 + ng * 16 + b_r) * ASTRIDE + k0 + b_c) * 2;
                ldsm4(bh[2 * ng][0], bh[2 * ng][1], bh[2 * ng + 1][0], bh[2 * ng + 1][1], bh_base + off);
            }
#pragma unroll
            for (int mt = 0; mt < 2; mt++)
#pragma unroll
                for (int nt = 0; nt < 8; nt++) {
                    mma_f16(acc[mt][nt], ah[mt], bh[nt]);
                    mma_f16(acc[mt][nt], al[mt], bh[nt]);
                }
        }
    }

#pragma unroll
    for (int mt = 0; mt < 2; mt++) {
#pragma unroll
        for (int nt = 0; nt < 8; nt++) {
            int c = colBase + wn * 64 + nt * 8 + (lane & 3) * 2;
            float b0 = bias[c], b1 = bias[c + 1];
#pragma unroll
            for (int h = 0; h < 2; h++) {
                int r = rowBase + wm * 32 + mt * 16 + (lane >> 2) + h * 8;
                if (r < M) {
                    float v0 = acc[mt][nt][2 * h + 0] + b0;
                    float v1 = acc[mt][nt][2 * h + 1] + b1;
                    if (act) { v0 = gelu_f(v0); v1 = gelu_f(v1); }
                    if (Cf) {
                        *(float2*)(Cf + (size_t)r * ncols + c) = make_float2(v0, v1);
                    } else {
                        __half h0, l0, h1, l1;
                        split_h(v0, h0, l0);
                        split_h(v1, h1, l1);
                        __half2 hh; hh.x = h0; hh.y = h1;
                        __half2 ll; ll.x = l0; ll.y = l1;
                        *(__half2*)(Chi + (size_t)r * ncols + c) = hh;
                        *(__half2*)(Clo + (size_t)r * ncols + c) = ll;
                    }
                }
            }
        }
    }
}

// ---------------- edge kernels: one warp per dst node, fused softmax-agg ----
__global__ __launch_bounds__(256) void edge128_k(
    const float* __restrict__ qp, const float* __restrict__ a,
    const float* __restrict__ bg)
{
    int gw = (blockIdx.x * 256 + threadIdx.x) >> 5;
    if (gw >= NN) return;
    int lane = threadIdx.x & 31;
    int c = lane * 4;
    float4 qv = *(const float4*)(qp + (size_t)gw * 256 + c);
    float4 av = *(const float4*)(a + c);
    float ax = 0.f, ay = 0.f, az = 0.f, aw = 0.f;
    float denom = 0.f;
    int i = g_rowptr[gw];
    int end = g_rowptr[gw + 1];
    if (i < end) {
        int s = g_esrc[i];
        float4 pv = *(const float4*)(qp + (size_t)s * 256 + 128 + c);
        while (1) {
            float4 pvn;
            if (i + 1 < end) {
                int sn = g_esrc[i + 1];
                pvn = *(const float4*)(qp + (size_t)sn * 256 + 128 + c);
            }
            float tx = qv.x + pv.x; tx = tx > 0.f ? tx : 0.2f * tx;
            float ty = qv.y + pv.y; ty = ty > 0.f ? ty : 0.2f * ty;
            float tz = qv.z + pv.z; tz = tz > 0.f ? tz : 0.2f * tz;
            float tw = qv.w + pv.w; tw = tw > 0.f ? tw : 0.2f * tw;
            float part = fmaf(tx, av.x, fmaf(ty, av.y, fmaf(tz, av.z, tw * av.w)));
#pragma unroll
            for (int off = 16; off > 0; off >>= 1)
                part += __shfl_xor_sync(0xffffffffu, part, off);
            float es = __expf(part);
            denom += es;
            ax = fmaf(es, pv.x, ax);
            ay = fmaf(es, pv.y, ay);
            az = fmaf(es, pv.z, az);
            aw = fmaf(es, pv.w, aw);
            i++;
            if (i >= end) break;
            pv = pvn;
        }
    }
    float inv = denom > 0.f ? 1.0f / denom : 0.f;
    float4 bv = *(const float4*)(bg + c);
    float o[4];
    o[0] = gelu_f(fmaf(ax, inv, bv.x));
    o[1] = gelu_f(fmaf(ay, inv, bv.y));
    o[2] = gelu_f(fmaf(az, inv, bv.z));
    o[3] = gelu_f(fmaf(aw, inv, bv.w));
    __half h[4], l[4];
#pragma unroll
    for (int j = 0; j < 4; j++) split_h(o[j], h[j], l[j]);
    __half2 hh0; hh0.x = h[0]; hh0.y = h[1];
    __half2 hh1; hh1.x = h[2]; hh1.y = h[3];
    __half2 ll0; ll0.x = l[0]; ll0.y = l[1];
    __half2 ll1; ll1.x = l[2]; ll1.y = l[3];
    *(__half2*)(g_m2hi + (size_t)gw * 128 + c) = hh0;
    *(__half2*)(g_m2hi + (size_t)gw * 128 + c + 2) = hh1;
    *(__half2*)(g_m2lo + (size_t)gw * 128 + c) = ll0;
    *(__half2*)(g_m2lo + (size_t)gw * 128 + c + 2) = ll1;
}

__global__ __launch_bounds__(256) void edge64_k(
    const float* __restrict__ qp, const float* __restrict__ a,
    const float* __restrict__ bo, float* __restrict__ out)
{
    int gw = (blockIdx.x * 256 + threadIdx.x) >> 5;
    if (gw >= NN) return;
    int lane = threadIdx.x & 31;
    int c = lane * 2;
    float2 qv = *(const float2*)(qp + (size_t)gw * 128 + c);
    float2 av = *(const float2*)(a + c);
    float ax = 0.f, ay = 0.f;
    float denom = 0.f;
    int i = g_rowptr[gw];
    int end = g_rowptr[gw + 1];
    if (i < end) {
        int s = g_esrc[i];
        float2 pv = *(const float2*)(qp + (size_t)s * 128 + 64 + c);
        while (1) {
            float2 pvn;
            if (i + 1 < end) {
                int sn = g_esrc[i + 1];
                pvn = *(const float2*)(qp + (size_t)sn * 128 + 64 + c);
            }
            float tx = qv.x + pv.x; tx = tx > 0.f ? tx : 0.2f * tx;
            float ty = qv.y + pv.y; ty = ty > 0.f ? ty : 0.2f * ty;
            float part = fmaf(tx, av.x, ty * av.y);
#pragma unroll
            for (int off = 16; off > 0; off >>= 1)
                part += __shfl_xor_sync(0xffffffffu, part, off);
            float es = __expf(part);
            denom += es;
            ax = fmaf(es, pv.x, ax);
            ay = fmaf(es, pv.y, ay);
            i++;
            if (i >= end) break;
            pv = pvn;
        }
    }
    float inv = denom > 0.f ? 1.0f / denom : 0.f;
    float2 bv = *(const float2*)(bo + c);
    float2 o;
    o.x = fmaf(ax, inv, bv.x);
    o.y = fmaf(ay, inv, bv.y);
    *(float2*)(out + (size_t)gw * 64 + c) = o;
}

// ---------------- launch ----------------
extern "C" void kernel_launch(void* const* d_in, const int* in_sizes, int n_in,
                              void* d_out, int out_size)
{
    const float* x    = (const float*)d_in[0];
    const float* W0   = (const float*)d_in[1];
    const float* b0   = (const float*)d_in[2];
    const float* Wq1  = (const float*)d_in[3];
    const float* bq1  = (const float*)d_in[4];
    const float* Wp1  = (const float*)d_in[5];
    const float* bp1  = (const float*)d_in[6];
    const float* a1   = (const float*)d_in[7];
    const float* bg2  = (const float*)d_in[8];
    const float* Wq2  = (const float*)d_in[9];
    const float* bq2  = (const float*)d_in[10];
    const float* Wp2  = (const float*)d_in[11];
    const float* bp2  = (const float*)d_in[12];
    const float* a2   = (const float*)d_in[13];
    const float* bout = (const float*)d_in[14];
    const int*   src  = (const int*)d_in[15];
    const int*   dst  = (const int*)d_in[16];
    float* out = (float*)d_out;

    __half *xhi, *xlo, *m1hi, *m1lo, *m2hi, *m2lo, *w0t, *wqp1t, *wqp2t;
    float *qp1, *qp2, *bqp1, *bqp2;
    cudaGetSymbolAddress((void**)&xhi, g_xhi);   cudaGetSymbolAddress((void**)&xlo, g_xlo);
    cudaGetSymbolAddress((void**)&m1hi, g_m1hi); cudaGetSymbolAddress((void**)&m1lo, g_m1lo);
    cudaGetSymbolAddress((void**)&m2hi, g_m2hi); cudaGetSymbolAddress((void**)&m2lo, g_m2lo);
    cudaGetSymbolAddress((void**)&w0t, g_w0t);
    cudaGetSymbolAddress((void**)&wqp1t, g_wqp1t);
    cudaGetSymbolAddress((void**)&wqp2t, g_wqp2t);
    cudaGetSymbolAddress((void**)&qp1, g_qp1); cudaGetSymbolAddress((void**)&qp2, g_qp2);
    cudaGetSymbolAddress((void**)&bqp1, g_bqp1); cudaGetSymbolAddress((void**)&bqp2, g_bqp2);

    constexpr int SMEM = 3 * ABUF;   // 104448 B
    cudaFuncSetAttribute(gemm_mma, cudaFuncAttributeMaxDynamicSharedMemorySize, SMEM);

    // ---- fork: CSR build runs on a side stream, overlapped with the GEMM chain ----
    cudaStream_t s2;
    cudaStreamCreateWithFlags(&s2, cudaStreamNonBlocking);
    cudaEvent_t evFork, evJoin;
    cudaEventCreateWithFlags(&evFork, cudaEventDisableTiming);
    cudaEventCreateWithFlags(&evJoin, cudaEventDisableTiming);

    cudaEventRecord(evFork, 0);
    cudaStreamWaitEvent(s2, evFork, 0);
    zero_k<<<(NN + 255) / 256, 256, 0, s2>>>();
    hist_k<<<(EE + 255) / 256, 256, 0, s2>>>(dst);
    scan_k<<<1, 1024, 0, s2>>>();
    scatter_k<<<(EE + 255) / 256, 256, 0, s2>>>(src, dst);
    cudaEventRecord(evJoin, s2);

    // ---- main chain: conversions + layer-1 GEMMs (independent of CSR) ----
    convx_k<<<(NN * 128 + 255) / 256, 256>>>(x);
    convw_k<<<(128 * 128 + 255) / 256, 256>>>(W0, W0, b0, b0, w0t, nullptr, 128, 0);
    convw_k<<<(256 * 128 + 255) / 256, 256>>>(Wq1, Wp1, bq1, bp1, wqp1t, bqp1, 128, 128);
    convw_k<<<(128 * 128 + 255) / 256, 256>>>(Wq2, Wp2, bq2, bp2, wqp2t, bqp2, 64, 64);

    const int MB = (NN + 127) / 128;

    gemm_mma<<<dim3(MB, 1), 256, SMEM>>>(xhi, xlo, w0t, b0,
                                         nullptr, m1hi, m1lo, NN, 128, 1);   // m1 (fp16 hi/lo)
    gemm_mma<<<dim3(MB, 2), 256, SMEM>>>(m1hi, m1lo, wqp1t, bqp1,
                                         qp1, nullptr, nullptr, NN, 256, 0); // q1|p1

    // ---- join: edge pass needs the CSR ----
    cudaStreamWaitEvent(0, evJoin, 0);
    edge128_k<<<(NN * 32 + 255) / 256, 256>>>(qp1, a1, bg2);                 // m2 (fp16 hi/lo)

    // layer 2
    gemm_mma<<<dim3(MB, 1), 256, SMEM>>>(m2hi, m2lo, wqp2t, bqp2,
                                         qp2, nullptr, nullptr, NN, 128, 0); // q2|p2
    edge64_k<<<(NN * 32 + 255) / 256, 256>>>(qp2, a2, bout, out);            // out
}

// round 8
// speedup vs baseline: 3.0871x; 1.0825x over previous
#include <cuda_runtime.h>
#include <cuda_fp16.h>
#include <cstdint>

#define NN 50000
#define EE 800000

// ---------------- scratch (static device globals; no allocs) ----------------
__device__ __half g_m2hi[NN * 128], g_m2lo[NN * 128];
__device__ float g_qp1[NN * 256];   // [node][0:128]=q1, [128:256]=p1
__device__ float g_qp2[NN * 128];   // [node][0:64]=q2, [64:128]=p2
__device__ __half g_w0t[128 * 128];
__device__ __half g_wqp1t[256 * 128];
__device__ __half g_wqp2t[128 * 128];
__device__ float g_bqp1[256];
__device__ float g_bqp2[128];
__device__ int   g_rowptr[NN + 1];
__device__ int   g_cursor[NN];
__device__ int   g_esrc[EE];

__device__ __forceinline__ float gelu_f(float x) {
    return 0.5f * x * (1.0f + erff(x * 0.70710678118654752440f));
}
__device__ __forceinline__ void split_h(float v, __half& hi, __half& lo) {
    hi = __float2half_rn(v);
    lo = __float2half_rn(v - __half2float(hi));
}
__device__ __forceinline__ uint32_t smem_u32(const void* p) {
    uint32_t a;
    asm("{ .reg .u64 t; cvta.to.shared.u64 t, %1; cvt.u32.u64 %0, t; }" : "=r"(a) : "l"(p));
    return a;
}
__device__ __forceinline__ void ldsm4(uint32_t& r0, uint32_t& r1, uint32_t& r2, uint32_t& r3, uint32_t addr) {
    asm volatile("ldmatrix.sync.aligned.m8n8.x4.shared.b16 {%0,%1,%2,%3}, [%4];"
                 : "=r"(r0), "=r"(r1), "=r"(r2), "=r"(r3) : "r"(addr));
}
__device__ __forceinline__ void mma_f16(float* c, const uint32_t* a, const uint32_t* b) {
    asm volatile(
        "mma.sync.aligned.m16n8k16.row.col.f32.f16.f16.f32 "
        "{%0,%1,%2,%3}, {%4,%5,%6,%7}, {%8,%9}, {%0,%1,%2,%3};"
        : "+f"(c[0]), "+f"(c[1]), "+f"(c[2]), "+f"(c[3])
        : "r"(a[0]), "r"(a[1]), "r"(a[2]), "r"(a[3]), "r"(b[0]), "r"(b[1]));
}
__device__ __forceinline__ void cp16(uint32_t saddr, const void* gaddr) {
    asm volatile("cp.async.cg.shared.global [%0], [%1], 16;" :: "r"(saddr), "l"(gaddr) : "memory");
}

#define ASTRIDE 136
#define ABUF (128 * ASTRIDE * 2)   // 34816 B per buffer

// full-K mainloop: acc += A(smem hi/lo) @ B(smem)^T for this warp's 32x64 tile
__device__ __forceinline__ void mainloop_f16(
    uint32_t ah_base, uint32_t al_base, uint32_t bh_base,
    int wm, int wn, int lane, float acc[2][8][4])
{
    const int a_r = (lane & 15);
    const int a_c = (lane >> 4) * 8;
    const int b_r = (lane & 7) + ((lane >> 4) << 3);
    const int b_c = ((lane >> 3) & 1) * 8;
#pragma unroll
    for (int ks = 0; ks < 8; ks++) {
        const int k0 = ks * 16;
        uint32_t ah[2][4], al[2][4];
#pragma unroll
        for (int mt = 0; mt < 2; mt++) {
            uint32_t off = (uint32_t)((wm * 32 + mt * 16 + a_r) * ASTRIDE + k0 + a_c) * 2;
            ldsm4(ah[mt][0], ah[mt][1], ah[mt][2], ah[mt][3], ah_base + off);
            ldsm4(al[mt][0], al[mt][1], al[mt][2], al[mt][3], al_base + off);
        }
        uint32_t bh[8][2];
#pragma unroll
        for (int ng = 0; ng < 4; ng++) {
            uint32_t off = (uint32_t)((wn * 64 + ng * 16 + b_r) * ASTRIDE + k0 + b_c) * 2;
            ldsm4(bh[2 * ng][0], bh[2 * ng][1], bh[2 * ng + 1][0], bh[2 * ng + 1][1], bh_base + off);
        }
#pragma unroll
        for (int mt = 0; mt < 2; mt++)
#pragma unroll
            for (int nt = 0; nt < 8; nt++) {
                mma_f16(acc[mt][nt], ah[mt], bh[nt]);
                mma_f16(acc[mt][nt], al[mt], bh[nt]);
            }
    }
}

// ---------------- CSR build ----------------
__global__ void zero_k() {
    int i = blockIdx.x * blockDim.x + threadIdx.x;
    if (i < NN) g_cursor[i] = 0;
}
__global__ void hist_k(const int* __restrict__ dst) {
    int e = blockIdx.x * blockDim.x + threadIdx.x;
    if (e < EE) atomicAdd(&g_cursor[dst[e]], 1);
}
__global__ __launch_bounds__(1024) void scan_k() {
    __shared__ int warpsum[32];
    __shared__ int s_carry;
    __shared__ int s_tot;
    int tid = threadIdx.x, lane = tid & 31, wid = tid >> 5;
    if (tid == 0) s_carry = 0;
    __syncthreads();
    for (int base = 0; base < NN; base += 8192) {
        int idx0 = base + tid * 8;
        int v[8]; int tot = 0;
#pragma unroll
        for (int j = 0; j < 8; j++) {
            int id = idx0 + j;
            v[j] = (id < NN) ? g_cursor[id] : 0;
            tot += v[j];
        }
        int incl = tot;
#pragma unroll
        for (int off = 1; off < 32; off <<= 1) {
            int t = __shfl_up_sync(0xffffffffu, incl, off);
            if (lane >= off) incl += t;
        }
        if (lane == 31) warpsum[wid] = incl;
        __syncthreads();
        if (wid == 0) {
            int w = warpsum[lane];
            int wi = w;
#pragma unroll
            for (int off = 1; off < 32; off <<= 1) {
                int t = __shfl_up_sync(0xffffffffu, wi, off);
                if (lane >= off) wi += t;
            }
            warpsum[lane] = wi - w;
            if (lane == 31) s_tot = wi;
        }
        __syncthreads();
        int run = s_carry + warpsum[wid] + (incl - tot);
#pragma unroll
        for (int j = 0; j < 8; j++) {
            int id = idx0 + j;
            if (id < NN) { g_rowptr[id] = run; g_cursor[id] = 0; }
            run += v[j];
        }
        __syncthreads();
        if (tid == 0) s_carry += s_tot;
        __syncthreads();
    }
    if (threadIdx.x == 0) g_rowptr[NN] = s_carry;
}
__global__ void scatter_k(const int* __restrict__ src, const int* __restrict__ dst) {
    int e = blockIdx.x * blockDim.x + threadIdx.x;
    if (e < EE) {
        int d = dst[e];
        int pos = g_rowptr[d] + atomicAdd(&g_cursor[d], 1);
        g_esrc[pos] = src[e];
    }
}

// ---------------- conversions ----------------
__global__ void convw_k(const float* __restrict__ Wa, const float* __restrict__ Wb,
                        const float* __restrict__ ba, const float* __restrict__ bb,
                        __half* __restrict__ Wt, float* __restrict__ bc, int na, int nb) {
    int nc = na + nb;
    int i = blockIdx.x * blockDim.x + threadIdx.x;
    if (i < nc * 128) {
        int n = i >> 7, k = i & 127;
        float v = (n < na) ? Wa[(size_t)k * na + n] : Wb[(size_t)k * nb + (n - na)];
        Wt[i] = __float2half_rn(v);
    }
    if (bc && i < nc) bc[i] = (i < na) ? ba[i] : bb[i - na];
}

// ---------------- fused layer-1: qp1 = gelu(x@W0+b0) @ Wqp1 + bqp1 ------------
// One CTA: 128 rows. Stage x (fp32 -> fp16 hi/lo smem), mainloop m1, gelu/split
// back to smem, then 2 column-halves of the qp1 GEMM with streamed W tiles.
__global__ __launch_bounds__(256, 2) void gemm_l1(
    const float* __restrict__ x, const __half* __restrict__ W0t,
    const float* __restrict__ b0, const __half* __restrict__ Wqp1t,
    const float* __restrict__ bqp1, float* __restrict__ qp1, int M)
{
    extern __shared__ char sm[];
    char* AH = sm;
    char* AL = sm + ABUF;
    char* BH = sm + 2 * ABUF;

    const int tid = threadIdx.x;
    const int warp = tid >> 5, lane = tid & 31;
    const int wm = warp >> 1, wn = warp & 1;
    const int rowBase = blockIdx.x * 128;

    const uint32_t ah_base = smem_u32(AH);
    const uint32_t al_base = smem_u32(AL);
    const uint32_t bh_base = smem_u32(BH);

    // ---- W0 via cp.async; x staged with in-register fp32->hi/lo conversion ----
#pragma unroll
    for (int it = 0; it < 8; it++) {
        int idx = tid + it * 256;               // 0..2047
        int row = idx >> 4, ch = idx & 15;
        uint32_t so = (uint32_t)(row * ASTRIDE + ch * 8) * 2;
        cp16(bh_base + so, W0t + (size_t)row * 128 + ch * 8);
    }
    asm volatile("cp.async.commit_group;" ::: "memory");
#pragma unroll
    for (int it = 0; it < 8; it++) {
        int idx = tid + it * 256;
        int row = idx >> 4, ch = idx & 15;
        int gr = rowBase + row; if (gr >= M) gr = M - 1;
        float4 v0 = *(const float4*)(x + (size_t)gr * 128 + ch * 8);
        float4 v1 = *(const float4*)(x + (size_t)gr * 128 + ch * 8 + 4);
        __half hh[8], ll[8];
        split_h(v0.x, hh[0], ll[0]); split_h(v0.y, hh[1], ll[1]);
        split_h(v0.z, hh[2], ll[2]); split_h(v0.w, hh[3], ll[3]);
        split_h(v1.x, hh[4], ll[4]); split_h(v1.y, hh[5], ll[5]);
        split_h(v1.z, hh[6], ll[6]); split_h(v1.w, hh[7], ll[7]);
        uint32_t so = (uint32_t)(row * ASTRIDE + ch * 8) * 2;
        *(uint4*)(AH + so) = *(const uint4*)hh;
        *(uint4*)(AL + so) = *(const uint4*)ll;
    }
    asm volatile("cp.async.wait_group 0;" ::: "memory");
    __syncthreads();

    float acc[2][8][4];
#pragma unroll
    for (int i = 0; i < 2; i++)
#pragma unroll
        for (int j = 0; j < 8; j++)
#pragma unroll
            for (int k = 0; k < 4; k++) acc[i][j][k] = 0.f;

    // ---- mainloop 1: m1 = x @ W0^T ----
    mainloop_f16(ah_base, al_base, bh_base, wm, wn, lane, acc);
    __syncthreads();   // everyone done reading AH/AL

    // ---- epilogue 1: gelu(m1+b0), split, write back into AH/AL ----
#pragma unroll
    for (int mt = 0; mt < 2; mt++)
#pragma unroll
        for (int nt = 0; nt < 8; nt++) {
            int c = wn * 64 + nt * 8 + (lane & 3) * 2;
            float bb0 = b0[c], bb1 = b0[c + 1];
#pragma unroll
            for (int h = 0; h < 2; h++) {
                int r = wm * 32 + mt * 16 + (lane >> 2) + h * 8;
                float v0 = gelu_f(acc[mt][nt][2 * h + 0] + bb0);
                float v1 = gelu_f(acc[mt][nt][2 * h + 1] + bb1);
                __half h0, l0, h1, l1;
                split_h(v0, h0, l0);
                split_h(v1, h1, l1);
                uint32_t so = (uint32_t)(r * ASTRIDE + c) * 2;
                __half2 hh; hh.x = h0; hh.y = h1;
                __half2 ll; ll.x = l0; ll.y = l1;
                *(__half2*)(AH + so) = hh;
                *(__half2*)(AL + so) = ll;
            }
        }
    __syncthreads();

    // ---- stage 2: two column-halves of qp1 = m1 @ Wqp1^T ----
#pragma unroll
    for (int cb = 0; cb < 2; cb++) {
#pragma unroll
        for (int it = 0; it < 8; it++) {
            int idx = tid + it * 256;
            int row = idx >> 4, ch = idx & 15;
            uint32_t so = (uint32_t)(row * ASTRIDE + ch * 8) * 2;
            cp16(bh_base + so, Wqp1t + (size_t)(cb * 128 + row) * 128 + ch * 8);
        }
        asm volatile("cp.async.commit_group;" ::: "memory");
        asm volatile("cp.async.wait_group 0;" ::: "memory");
        __syncthreads();

#pragma unroll
        for (int i = 0; i < 2; i++)
#pragma unroll
            for (int j = 0; j < 8; j++)
#pragma unroll
                for (int k = 0; k < 4; k++) acc[i][j][k] = 0.f;
        mainloop_f16(ah_base, al_base, bh_base, wm, wn, lane, acc);

#pragma unroll
        for (int mt = 0; mt < 2; mt++)
#pragma unroll
            for (int nt = 0; nt < 8; nt++) {
                int c = cb * 128 + wn * 64 + nt * 8 + (lane & 3) * 2;
                float bb0 = bqp1[c], bb1 = bqp1[c + 1];
#pragma unroll
                for (int h = 0; h < 2; h++) {
                    int r = rowBase + wm * 32 + mt * 16 + (lane >> 2) + h * 8;
                    if (r < M) {
                        float v0 = acc[mt][nt][2 * h + 0] + bb0;
                        float v1 = acc[mt][nt][2 * h + 1] + bb1;
                        *(float2*)(qp1 + (size_t)r * 256 + c) = make_float2(v0, v1);
                    }
                }
            }
        if (cb == 0) __syncthreads();   // before overwriting BH
    }
}

// ---------------- layer-2 GEMM (reads m2 hi/lo, writes qp2) ------------------
__global__ __launch_bounds__(256, 2) void gemm_mma(
    const __half* __restrict__ Ahi, const __half* __restrict__ Alo,
    const __half* __restrict__ Bh, const float* __restrict__ bias,
    float* __restrict__ Cf, int M, int ncols)
{
    extern __shared__ char sm[];
    char* AH = sm;
    char* AL = sm + ABUF;
    char* BH = sm + 2 * ABUF;

    const int tid = threadIdx.x;
    const int warp = tid >> 5, lane = tid & 31;
    const int wm = warp >> 1, wn = warp & 1;
    const int rowBase = blockIdx.x * 128;
    const int colBase = blockIdx.y * 128;

    const uint32_t ah_base = smem_u32(AH);
    const uint32_t al_base = smem_u32(AL);
    const uint32_t bh_base = smem_u32(BH);

#pragma unroll
    for (int it = 0; it < 8; it++) {
        int idx = tid + it * 256;
        int row = idx >> 4, ch = idx & 15;
        int gr = rowBase + row; if (gr >= M) gr = M - 1;
        uint32_t so = (uint32_t)(row * ASTRIDE + ch * 8) * 2;
        cp16(ah_base + so, Ahi + (size_t)gr * 128 + ch * 8);
        cp16(al_base + so, Alo + (size_t)gr * 128 + ch * 8);
        int gn = colBase + row;
        cp16(bh_base + so, Bh + (size_t)gn * 128 + ch * 8);
    }
    asm volatile("cp.async.commit_group;" ::: "memory");
    asm volatile("cp.async.wait_group 0;" ::: "memory");
    __syncthreads();

    float acc[2][8][4];
#pragma unroll
    for (int i = 0; i < 2; i++)
#pragma unroll
        for (int j = 0; j < 8; j++)
#pragma unroll
            for (int k = 0; k < 4; k++) acc[i][j][k] = 0.f;
    mainloop_f16(ah_base, al_base, bh_base, wm, wn, lane, acc);

#pragma unroll
    for (int mt = 0; mt < 2; mt++)
#pragma unroll
        for (int nt = 0; nt < 8; nt++) {
            int c = colBase + wn * 64 + nt * 8 + (lane & 3) * 2;
            float b0 = bias[c], b1 = bias[c + 1];
#pragma unroll
            for (int h = 0; h < 2; h++) {
                int r = rowBase + wm * 32 + mt * 16 + (lane >> 2) + h * 8;
                if (r < M) {
                    float v0 = acc[mt][nt][2 * h + 0] + b0;
                    float v1 = acc[mt][nt][2 * h + 1] + b1;
                    *(float2*)(Cf + (size_t)r * ncols + c) = make_float2(v0, v1);
                }
            }
        }
}

// ---------------- edge kernels ----------------
__global__ __launch_bounds__(256) void edge128_k(
    const float* __restrict__ qp, const float* __restrict__ a,
    const float* __restrict__ bg)
{
    int gw = (blockIdx.x * 256 + threadIdx.x) >> 5;
    if (gw >= NN) return;
    int lane = threadIdx.x & 31;
    int c = lane * 4;
    float4 qv = *(const float4*)(qp + (size_t)gw * 256 + c);
    float4 av = *(const float4*)(a + c);
    float ax = 0.f, ay = 0.f, az = 0.f, aw = 0.f;
    float denom = 0.f;
    int i = g_rowptr[gw];
    int end = g_rowptr[gw + 1];
    if (i < end) {
        int s = g_esrc[i];
        float4 pv = *(const float4*)(qp + (size_t)s * 256 + 128 + c);
        while (1) {
            float4 pvn;
            if (i + 1 < end) {
                int sn = g_esrc[i + 1];
                pvn = *(const float4*)(qp + (size_t)sn * 256 + 128 + c);
            }
            float tx = qv.x + pv.x; tx = tx > 0.f ? tx : 0.2f * tx;
            float ty = qv.y + pv.y; ty = ty > 0.f ? ty : 0.2f * ty;
            float tz = qv.z + pv.z; tz = tz > 0.f ? tz : 0.2f * tz;
            float tw = qv.w + pv.w; tw = tw > 0.f ? tw : 0.2f * tw;
            float part = fmaf(tx, av.x, fmaf(ty, av.y, fmaf(tz, av.z, tw * av.w)));
#pragma unroll
            for (int off = 16; off > 0; off >>= 1)
                part += __shfl_xor_sync(0xffffffffu, part, off);
            float es = __expf(part);
            denom += es;
            ax = fmaf(es, pv.x, ax);
            ay = fmaf(es, pv.y, ay);
            az = fmaf(es, pv.z, az);
            aw = fmaf(es, pv.w, aw);
            i++;
            if (i >= end) break;
            pv = pvn;
        }
    }
    float inv = denom > 0.f ? 1.0f / denom : 0.f;
    float4 bv = *(const float4*)(bg + c);
    float o[4];
    o[0] = gelu_f(fmaf(ax, inv, bv.x));
    o[1] = gelu_f(fmaf(ay, inv, bv.y));
    o[2] = gelu_f(fmaf(az, inv, bv.z));
    o[3] = gelu_f(fmaf(aw, inv, bv.w));
    __half h[4], l[4];
#pragma unroll
    for (int j = 0; j < 4; j++) split_h(o[j], h[j], l[j]);
    __half2 hh0; hh0.x = h[0]; hh0.y = h[1];
    __half2 hh1; hh1.x = h[2]; hh1.y = h[3];
    __half2 ll0; ll0.x = l[0]; ll0.y = l[1];
    __half2 ll1; ll1.x = l[2]; ll1.y = l[3];
    *(__half2*)(g_m2hi + (size_t)gw * 128 + c) = hh0;
    *(__half2*)(g_m2hi + (size_t)gw * 128 + c + 2) = hh1;
    *(__half2*)(g_m2lo + (size_t)gw * 128 + c) = ll0;
    *(__half2*)(g_m2lo + (size_t)gw * 128 + c + 2) = ll1;
}

__global__ __launch_bounds__(256) void edge64_k(
    const float* __restrict__ qp, const float* __restrict__ a,
    const float* __restrict__ bo, float* __restrict__ out)
{
    int gw = (blockIdx.x * 256 + threadIdx.x) >> 5;
    if (gw >= NN) return;
    int lane = threadIdx.x & 31;
    int c = lane * 2;
    float2 qv = *(const float2*)(qp + (size_t)gw * 128 + c);
    float2 av = *(const float2*)(a + c);
    float ax = 0.f, ay = 0.f;
    float denom = 0.f;
    int i = g_rowptr[gw];
    int end = g_rowptr[gw + 1];
    if (i < end) {
        int s = g_esrc[i];
        float2 pv = *(const float2*)(qp + (size_t)s * 128 + 64 + c);
        while (1) {
            float2 pvn;
            if (i + 1 < end) {
                int sn = g_esrc[i + 1];
                pvn = *(const float2*)(qp + (size_t)sn * 128 + 64 + c);
            }
            float tx = qv.x + pv.x; tx = tx > 0.f ? tx : 0.2f * tx;
            float ty = qv.y + pv.y; ty = ty > 0.f ? ty : 0.2f * ty;
            float part = fmaf(tx, av.x, ty * av.y);
#pragma unroll
            for (int off = 16; off > 0; off >>= 1)
                part += __shfl_xor_sync(0xffffffffu, part, off);
            float es = __expf(part);
            denom += es;
            ax = fmaf(es, pv.x, ax);
            ay = fmaf(es, pv.y, ay);
            i++;
            if (i >= end) break;
            pv = pvn;
        }
    }
    float inv = denom > 0.f ? 1.0f / denom : 0.f;
    float2 bv = *(const float2*)(bo + c);
    float2 o;
    o.x = fmaf(ax, inv, bv.x);
    o.y = fmaf(ay, inv, bv.y);
    *(float2*)(out + (size_t)gw * 64 + c) = o;
}

// ---------------- launch ----------------
extern "C" void kernel_launch(void* const* d_in, const int* in_sizes, int n_in,
                              void* d_out, int out_size)
{
    const float* x    = (const float*)d_in[0];
    const float* W0   = (const float*)d_in[1];
    const float* b0   = (const float*)d_in[2];
    const float* Wq1  = (const float*)d_in[3];
    const float* bq1  = (const float*)d_in[4];
    const float* Wp1  = (const float*)d_in[5];
    const float* bp1  = (const float*)d_in[6];
    const float* a1   = (const float*)d_in[7];
    const float* bg2  = (const float*)d_in[8];
    const float* Wq2  = (const float*)d_in[9];
    const float* bq2  = (const float*)d_in[10];
    const float* Wp2  = (const float*)d_in[11];
    const float* bp2  = (const float*)d_in[12];
    const float* a2   = (const float*)d_in[13];
    const float* bout = (const float*)d_in[14];
    const int*   src  = (const int*)d_in[15];
    const int*   dst  = (const int*)d_in[16];
    float* out = (float*)d_out;

    __half *m2hi, *m2lo, *w0t, *wqp1t, *wqp2t;
    float *qp1, *qp2, *bqp1, *bqp2;
    cudaGetSymbolAddress((void**)&m2hi, g_m2hi); cudaGetSymbolAddress((void**)&m2lo, g_m2lo);
    cudaGetSymbolAddress((void**)&w0t, g_w0t);
    cudaGetSymbolAddress((void**)&wqp1t, g_wqp1t);
    cudaGetSymbolAddress((void**)&wqp2t, g_wqp2t);
    cudaGetSymbolAddress((void**)&qp1, g_qp1); cudaGetSymbolAddress((void**)&qp2, g_qp2);
    cudaGetSymbolAddress((void**)&bqp1, g_bqp1); cudaGetSymbolAddress((void**)&bqp2, g_bqp2);

    constexpr int SMEM = 3 * ABUF;   // 104448 B
    cudaFuncSetAttribute(gemm_l1, cudaFuncAttributeMaxDynamicSharedMemorySize, SMEM);
    cudaFuncSetAttribute(gemm_mma, cudaFuncAttributeMaxDynamicSharedMemorySize, SMEM);

    // ---- fork: CSR build on side stream, hidden under the GEMM chain ----
    cudaStream_t s2;
    cudaStreamCreateWithFlags(&s2, cudaStreamNonBlocking);
    cudaEvent_t evFork, evJoin;
    cudaEventCreateWithFlags(&evFork, cudaEventDisableTiming);
    cudaEventCreateWithFlags(&evJoin, cudaEventDisableTiming);

    cudaEventRecord(evFork, 0);
    cudaStreamWaitEvent(s2, evFork, 0);
    zero_k<<<(NN + 255) / 256, 256, 0, s2>>>();
    hist_k<<<(EE + 255) / 256, 256, 0, s2>>>(dst);
    scan_k<<<1, 1024, 0, s2>>>();
    scatter_k<<<(EE + 255) / 256, 256, 0, s2>>>(src, dst);
    cudaEventRecord(evJoin, s2);

    // ---- main chain ----
    convw_k<<<(128 * 128 + 255) / 256, 256>>>(W0, W0, b0, b0, w0t, nullptr, 128, 0);
    convw_k<<<(256 * 128 + 255) / 256, 256>>>(Wq1, Wp1, bq1, bp1, wqp1t, bqp1, 128, 128);
    convw_k<<<(128 * 128 + 255) / 256, 256>>>(Wq2, Wp2, bq2, bp2, wqp2t, bqp2, 64, 64);

    const int MB = (NN + 127) / 128;

    // fused layer-1: qp1 = gelu(x@W0+b0) @ Wqp1 + bqp1
    gemm_l1<<<MB, 256, SMEM>>>(x, w0t, b0, wqp1t, bqp1, qp1, NN);

    // join: edge pass needs the CSR
    cudaStreamWaitEvent(0, evJoin, 0);
    edge128_k<<<(NN * 32 + 255) / 256, 256>>>(qp1, a1, bg2);       // m2 (fp16 hi/lo)

    // layer 2
    gemm_mma<<<dim3(MB, 1), 256, SMEM>>>(m2hi, m2lo, wqp2t, bqp2, qp2, NN, 128);
    edge64_k<<<(NN * 32 + 255) / 256, 256>>>(qp2, a2, bout, out);
}